// round 3
// baseline (speedup 1.0000x reference)
#include <cuda_runtime.h>
#include <cuda_bf16.h>
#include <math.h>

// Problem constants
#define BB 8
#define TT 1024
#define DD 1024
#define HH 16
#define DH 64
#define MROWS (BB*TT)   // 8192

// Scratch (static device allocations are allowed)
__device__ float g_q[MROWS * DD];    // (B,H,T,DH) layout
__device__ float g_k[MROWS * DD];    // (B,H,T,DH) layout
__device__ float g_v[MROWS * DD];    // (B,H,T,DH) layout
__device__ float g_ctx[MROWS * DD];  // (B,T,D) layout (attention output, pre-Wo)

// ---------------------------------------------------------------------------
// Tiled fp32 GEMM: C[M=8192, N=1024] = A[8192,1024] @ W[1024,1024] + bias
// MODE 0: scatter to (B,H,T,DH) head layout (for Q/K/V)
// MODE 1: plain row-major (final output)
// BM=BN=128, BK=16, 256 threads, 8x8 per-thread micro-tile.
// ---------------------------------------------------------------------------
template<int MODE>
__global__ __launch_bounds__(256)
void gemm_kernel(const float* __restrict__ A, const float* __restrict__ W,
                 const float* __restrict__ bias, float* __restrict__ out)
{
    __shared__ float As[16][132];  // [k][m], padded
    __shared__ float Bs[16][132];  // [k][n], padded

    const int tid = threadIdx.x;
    const int tx = tid & 15;
    const int ty = tid >> 4;
    const int m0 = blockIdx.y * 128;
    const int n0 = blockIdx.x * 128;

    float acc[8][8];
#pragma unroll
    for (int i = 0; i < 8; i++)
#pragma unroll
        for (int j = 0; j < 8; j++) acc[i][j] = 0.0f;

    for (int k0 = 0; k0 < DD; k0 += 16) {
        // A tile: 128 rows x 16 cols -> As[k][m] (transposed store)
#pragma unroll
        for (int it = 0; it < 2; it++) {
            int idx = tid + it * 256;          // 512 float4 slots
            int m  = idx >> 2;                 // 0..127
            int kk = (idx & 3) << 2;           // 0,4,8,12
            float4 v = *(const float4*)&A[(size_t)(m0 + m) * DD + k0 + kk];
            As[kk + 0][m] = v.x;
            As[kk + 1][m] = v.y;
            As[kk + 2][m] = v.z;
            As[kk + 3][m] = v.w;
        }
        // B tile: 16 rows x 128 cols
#pragma unroll
        for (int it = 0; it < 2; it++) {
            int idx = tid + it * 256;          // 512 float4 slots: 16 x 32
            int kk = idx >> 5;
            int nn = (idx & 31) << 2;
            *(float4*)&Bs[kk][nn] = *(const float4*)&W[(size_t)(k0 + kk) * DD + n0 + nn];
        }
        __syncthreads();

#pragma unroll
        for (int kk = 0; kk < 16; kk++) {
            float a[8], b[8];
            *(float4*)&a[0] = *(float4*)&As[kk][ty * 8];
            *(float4*)&a[4] = *(float4*)&As[kk][ty * 8 + 4];
            *(float4*)&b[0] = *(float4*)&Bs[kk][tx * 8];
            *(float4*)&b[4] = *(float4*)&Bs[kk][tx * 8 + 4];
#pragma unroll
            for (int i = 0; i < 8; i++)
#pragma unroll
                for (int j = 0; j < 8; j++)
                    acc[i][j] = fmaf(a[i], b[j], acc[i][j]);
        }
        __syncthreads();
    }

    // Epilogue
#pragma unroll
    for (int i = 0; i < 8; i++) {
        int m = m0 + ty * 8 + i;
        int bidx = m >> 10;     // /T
        int t = m & (TT - 1);
#pragma unroll
        for (int j = 0; j < 8; j++) {
            int n = n0 + tx * 8 + j;
            float v = acc[i][j] + bias[n];
            if (MODE == 0) {
                int h = n >> 6;       // /DH
                int d = n & (DH - 1);
                out[(((size_t)(bidx * HH + h) << 10) + t) * DH + d] = v;
            } else {
                out[(size_t)m * DD + n] = v;
            }
        }
    }
}

// ---------------------------------------------------------------------------
// Fused attention: per block handles (b, h, 64 query rows).
// Flash-attention style online softmax, fp32, bias = spatial+edge, mask->-1e30.
// 256 threads, 16x16 layout, 4x4 micro-tile of the 64x64 S / O tiles.
// Reads g_q/g_k/g_v (B,H,T,DH); writes g_ctx (B,T,D).
// mask is read as 4-byte elements (bool upcast by harness to int32/float32);
// nonzero bit pattern == True in either encoding.
// ---------------------------------------------------------------------------
#define APITCH 68

__global__ __launch_bounds__(256)
void attn_kernel(const float* __restrict__ sp, const float* __restrict__ ed,
                 const unsigned int* __restrict__ mask)
{
    extern __shared__ float sm[];
    float* Qs = sm;                    // 64 x APITCH
    float* Ks = Qs + 64 * APITCH;
    float* Vs = Ks + 64 * APITCH;
    float* BP = Vs + 64 * APITCH;      // bias tile, then reused as P tile

    const int tid = threadIdx.x;
    const int tx = tid & 15;
    const int ty = tid >> 4;
    const int q0 = blockIdx.x * 64;
    const int h  = blockIdx.y;
    const int b  = blockIdx.z;

    const float* Qg = g_q + (size_t)(b * HH + h) * TT * DH;
    const float* Kg = g_k + (size_t)(b * HH + h) * TT * DH;
    const float* Vg = g_v + (size_t)(b * HH + h) * TT * DH;

    // Load Q tile (64x64)
    for (int i = tid; i < 64 * 16; i += 256) {
        int r = i >> 4;
        int c4 = (i & 15) << 2;
        *(float4*)&Qs[r * APITCH + c4] = *(const float4*)&Qg[(size_t)(q0 + r) * DH + c4];
    }

    float m_run[4], l_run[4], O[4][4];
#pragma unroll
    for (int i = 0; i < 4; i++) {
        m_run[i] = -1e38f;
        l_run[i] = 0.0f;
#pragma unroll
        for (int j = 0; j < 4; j++) O[i][j] = 0.0f;
    }

    for (int kt = 0; kt < 16; kt++) {
        const int k0 = kt * 64;
        // K / V tiles
        for (int i = tid; i < 64 * 16; i += 256) {
            int r = i >> 4;
            int c4 = (i & 15) << 2;
            *(float4*)&Ks[r * APITCH + c4] = *(const float4*)&Kg[(size_t)(k0 + r) * DH + c4];
            *(float4*)&Vs[r * APITCH + c4] = *(const float4*)&Vg[(size_t)(k0 + r) * DH + c4];
        }
        // bias tile (spatial + edge, masked)
        for (int i = tid; i < 64 * 64; i += 256) {
            int r = i >> 6;
            int c = i & 63;
            int kg = k0 + c;
            size_t bij = ((size_t)b * TT + (q0 + r)) * TT + kg;
            float bv = (mask[b * TT + kg] != 0u) ? -1e30f : (sp[bij] + ed[bij]);
            BP[r * APITCH + c] = bv;
        }
        __syncthreads();

        // S = Q K^T
        float S[4][4];
#pragma unroll
        for (int i = 0; i < 4; i++)
#pragma unroll
            for (int j = 0; j < 4; j++) S[i][j] = 0.0f;

#pragma unroll 4
        for (int d = 0; d < 64; d += 4) {
            float4 qv[4], kv[4];
#pragma unroll
            for (int i = 0; i < 4; i++) qv[i] = *(float4*)&Qs[(ty * 4 + i) * APITCH + d];
#pragma unroll
            for (int j = 0; j < 4; j++) kv[j] = *(float4*)&Ks[(tx * 4 + j) * APITCH + d];
#pragma unroll
            for (int i = 0; i < 4; i++)
#pragma unroll
                for (int j = 0; j < 4; j++) {
                    S[i][j] = fmaf(qv[i].x, kv[j].x, S[i][j]);
                    S[i][j] = fmaf(qv[i].y, kv[j].y, S[i][j]);
                    S[i][j] = fmaf(qv[i].z, kv[j].z, S[i][j]);
                    S[i][j] = fmaf(qv[i].w, kv[j].w, S[i][j]);
                }
        }

        // scale + bias
#pragma unroll
        for (int i = 0; i < 4; i++)
#pragma unroll
            for (int j = 0; j < 4; j++)
                S[i][j] = S[i][j] * 0.125f + BP[(ty * 4 + i) * APITCH + tx * 4 + j];

        // online softmax update
#pragma unroll
        for (int i = 0; i < 4; i++) {
            float mt = fmaxf(fmaxf(S[i][0], S[i][1]), fmaxf(S[i][2], S[i][3]));
#pragma unroll
            for (int off = 8; off >= 1; off >>= 1)
                mt = fmaxf(mt, __shfl_xor_sync(0xffffffffu, mt, off));
            float m_new = fmaxf(m_run[i], mt);
            float alpha = __expf(m_run[i] - m_new);
            float lt = 0.0f;
#pragma unroll
            for (int j = 0; j < 4; j++) {
                float p = __expf(S[i][j] - m_new);
                S[i][j] = p;
                lt += p;
            }
#pragma unroll
            for (int off = 8; off >= 1; off >>= 1)
                lt += __shfl_xor_sync(0xffffffffu, lt, off);
            l_run[i] = l_run[i] * alpha + lt;
            m_run[i] = m_new;
#pragma unroll
            for (int j = 0; j < 4; j++) O[i][j] *= alpha;
        }

        // store P into BP (same slots this thread read its bias from)
#pragma unroll
        for (int i = 0; i < 4; i++)
#pragma unroll
            for (int j = 0; j < 4; j++)
                BP[(ty * 4 + i) * APITCH + tx * 4 + j] = S[i][j];
        __syncthreads();

        // O += P @ V
#pragma unroll 4
        for (int k = 0; k < 64; k++) {
            float4 vv = *(float4*)&Vs[k * APITCH + tx * 4];
#pragma unroll
            for (int i = 0; i < 4; i++) {
                float p = BP[(ty * 4 + i) * APITCH + k];
                O[i][0] = fmaf(p, vv.x, O[i][0]);
                O[i][1] = fmaf(p, vv.y, O[i][1]);
                O[i][2] = fmaf(p, vv.z, O[i][2]);
                O[i][3] = fmaf(p, vv.w, O[i][3]);
            }
        }
        __syncthreads();
    }

    // normalize + write to g_ctx (B,T,D)
#pragma unroll
    for (int i = 0; i < 4; i++) {
        float inv = 1.0f / l_run[i];
        float4 o4;
        o4.x = O[i][0] * inv;
        o4.y = O[i][1] * inv;
        o4.z = O[i][2] * inv;
        o4.w = O[i][3] * inv;
        size_t row = (size_t)b * TT + (q0 + ty * 4 + i);
        *(float4*)&g_ctx[row * DD + h * DH + tx * 4] = o4;
    }
}

// ---------------------------------------------------------------------------
// kernel_launch
// Inputs (metadata order): query, key, value, spatial_encoding, edge_encoding,
//   key_padding_mask, Wq, bq, Wk, bk, Wv, bv, Wo, bo
// ---------------------------------------------------------------------------
extern "C" void kernel_launch(void* const* d_in, const int* in_sizes, int n_in,
                              void* d_out, int out_size)
{
    const float* query = (const float*)d_in[0];
    const float* key_  = (const float*)d_in[1];
    const float* value = (const float*)d_in[2];
    const float* sp    = (const float*)d_in[3];
    const float* edg   = (const float*)d_in[4];
    const unsigned int* mask = (const unsigned int*)d_in[5];
    const float* Wq = (const float*)d_in[6];
    const float* bq = (const float*)d_in[7];
    const float* Wk = (const float*)d_in[8];
    const float* bk = (const float*)d_in[9];
    const float* Wv = (const float*)d_in[10];
    const float* bv = (const float*)d_in[11];
    const float* Wo = (const float*)d_in[12];
    const float* bo = (const float*)d_in[13];
    float* out = (float*)d_out;

    float* gq;  cudaGetSymbolAddress((void**)&gq, g_q);
    float* gk;  cudaGetSymbolAddress((void**)&gk, g_k);
    float* gv;  cudaGetSymbolAddress((void**)&gv, g_v);
    float* gctx; cudaGetSymbolAddress((void**)&gctx, g_ctx);

    dim3 gemm_grid(DD / 128, MROWS / 128);  // (8, 64)
    gemm_kernel<0><<<gemm_grid, 256>>>(query, Wq, bq, gq);
    gemm_kernel<0><<<gemm_grid, 256>>>(key_,  Wk, bk, gk);
    gemm_kernel<0><<<gemm_grid, 256>>>(value, Wv, bv, gv);

    const int attn_smem = 4 * 64 * APITCH * (int)sizeof(float);  // 69632 B
    cudaFuncSetAttribute(attn_kernel, cudaFuncAttributeMaxDynamicSharedMemorySize, attn_smem);
    dim3 attn_grid(TT / 64, HH, BB);  // (16, 16, 8)
    attn_kernel<<<attn_grid, 256, attn_smem>>>(sp, edg, mask);

    gemm_kernel<1><<<gemm_grid, 256>>>(gctx, Wo, bo, out);
}

// round 4
// speedup vs baseline: 3.5198x; 3.5198x over previous
#include <cuda_runtime.h>
#include <math.h>

// Problem constants
#define BB 8
#define TT 1024
#define DD 1024
#define HH 16
#define DHX 64
#define MROWS (BB*TT)   // 8192

// Scratch
__device__ float g_q[MROWS * DD];    // (B,H,T,DH)
__device__ float g_k[MROWS * DD];    // (B,H,T,DH)
__device__ float g_v[MROWS * DD];    // (B,H,T,DH)
__device__ float g_ctx[MROWS * DD];  // (B,T,D)

// ---------------------------------------------------------------------------
// helpers: tf32 convert (round-to-nearest -- REQUIRED, truncation biases the
// K=1024 dot products by ~2.5e-3) and m16n8k8 tf32 mma
// ---------------------------------------------------------------------------
__device__ __forceinline__ unsigned f2tf(float f) {
    unsigned u;
    asm("cvt.rna.tf32.f32 %0, %1;" : "=r"(u) : "f"(f));
    return u;
}

__device__ __forceinline__ void mma8(float& c0, float& c1, float& c2, float& c3,
                                     unsigned a0, unsigned a1, unsigned a2, unsigned a3,
                                     unsigned b0, unsigned b1) {
    asm("mma.sync.aligned.m16n8k8.row.col.f32.tf32.tf32.f32 "
        "{%0,%1,%2,%3}, {%4,%5,%6,%7}, {%8,%9}, {%0,%1,%2,%3};"
        : "+f"(c0), "+f"(c1), "+f"(c2), "+f"(c3)
        : "r"(a0), "r"(a1), "r"(a2), "r"(a3), "r"(b0), "r"(b1));
}

// ---------------------------------------------------------------------------
// tf32 tensor-core GEMM: C[8192,1024] = A @ W + bias
// BM=128 BN=128 BK=16, 256 threads = 8 warps (4m x 2n), warp tile 32x64.
// Double-buffered smem, LDG->cvt(rna)->STS pipeline, 1 sync/iter.
// MODE 0: scatter to (B,H,T,DH); MODE 1: row-major.
// Smem pitches: A pitch 20 (banks 20g+t distinct), W pitch 136 (8t+g bijective).
// ---------------------------------------------------------------------------
#define GPA 20
#define GPW 136

template<int MODE>
__global__ __launch_bounds__(256, 2)
void gemm_tc(const float* __restrict__ A, const float* __restrict__ W,
             const float* __restrict__ bias, float* __restrict__ out)
{
    __shared__ unsigned As[2][128 * GPA];
    __shared__ unsigned Ws[2][16 * GPW];

    const int tid  = threadIdx.x;
    const int lane = tid & 31;
    const int warp = tid >> 5;
    const int g = lane >> 2;     // 0..7
    const int t = lane & 3;      // 0..3
    const int wm = warp >> 1;    // 0..3 (m)
    const int wn = warp & 1;     // 0..1 (n)
    const int m0 = blockIdx.y * 128;
    const int n0 = blockIdx.x * 128;

    float4 ra[2], rw[2];

    // prologue: tile 0
#pragma unroll
    for (int it = 0; it < 2; it++) {
        int idx = tid + it * 256;
        ra[it] = *(const float4*)&A[(size_t)(m0 + (idx >> 2)) * DD + ((idx & 3) << 2)];
        rw[it] = *(const float4*)&W[(size_t)(idx >> 5) * DD + n0 + ((idx & 31) << 2)];
    }
#pragma unroll
    for (int it = 0; it < 2; it++) {
        int idx = tid + it * 256;
        unsigned* pa = &As[0][(idx >> 2) * GPA + ((idx & 3) << 2)];
        pa[0] = f2tf(ra[it].x); pa[1] = f2tf(ra[it].y); pa[2] = f2tf(ra[it].z); pa[3] = f2tf(ra[it].w);
        unsigned* pw = &Ws[0][(idx >> 5) * GPW + ((idx & 31) << 2)];
        pw[0] = f2tf(rw[it].x); pw[1] = f2tf(rw[it].y); pw[2] = f2tf(rw[it].z); pw[3] = f2tf(rw[it].w);
    }
    __syncthreads();

    float acc[2][8][4];
#pragma unroll
    for (int i = 0; i < 2; i++)
#pragma unroll
        for (int j = 0; j < 8; j++)
#pragma unroll
            for (int c = 0; c < 4; c++) acc[i][j][c] = 0.0f;

    for (int kt = 0; kt < 64; kt++) {
        const int cur = kt & 1;
        if (kt + 1 < 64) {
            const int k0 = (kt + 1) * 16;
#pragma unroll
            for (int it = 0; it < 2; it++) {
                int idx = tid + it * 256;
                ra[it] = *(const float4*)&A[(size_t)(m0 + (idx >> 2)) * DD + k0 + ((idx & 3) << 2)];
                rw[it] = *(const float4*)&W[(size_t)(k0 + (idx >> 5)) * DD + n0 + ((idx & 31) << 2)];
            }
        }

#pragma unroll
        for (int ks = 0; ks < 16; ks += 8) {
            unsigned af[2][4], bf[8][2];
#pragma unroll
            for (int i = 0; i < 2; i++) {
                int mb = wm * 32 + i * 16;
                af[i][0] = As[cur][(mb + g) * GPA + ks + t];
                af[i][1] = As[cur][(mb + g + 8) * GPA + ks + t];
                af[i][2] = As[cur][(mb + g) * GPA + ks + t + 4];
                af[i][3] = As[cur][(mb + g + 8) * GPA + ks + t + 4];
            }
#pragma unroll
            for (int j = 0; j < 8; j++) {
                int nb = wn * 64 + j * 8;
                bf[j][0] = Ws[cur][(ks + t) * GPW + nb + g];
                bf[j][1] = Ws[cur][(ks + t + 4) * GPW + nb + g];
            }
#pragma unroll
            for (int i = 0; i < 2; i++)
#pragma unroll
                for (int j = 0; j < 8; j++)
                    mma8(acc[i][j][0], acc[i][j][1], acc[i][j][2], acc[i][j][3],
                         af[i][0], af[i][1], af[i][2], af[i][3],
                         bf[j][0], bf[j][1]);
        }

        if (kt + 1 < 64) {
            const int nxt = (kt + 1) & 1;
#pragma unroll
            for (int it = 0; it < 2; it++) {
                int idx = tid + it * 256;
                unsigned* pa = &As[nxt][(idx >> 2) * GPA + ((idx & 3) << 2)];
                pa[0] = f2tf(ra[it].x); pa[1] = f2tf(ra[it].y); pa[2] = f2tf(ra[it].z); pa[3] = f2tf(ra[it].w);
                unsigned* pw = &Ws[nxt][(idx >> 5) * GPW + ((idx & 31) << 2)];
                pw[0] = f2tf(rw[it].x); pw[1] = f2tf(rw[it].y); pw[2] = f2tf(rw[it].z); pw[3] = f2tf(rw[it].w);
            }
        }
        __syncthreads();
    }

    // epilogue
#pragma unroll
    for (int i = 0; i < 2; i++) {
#pragma unroll
        for (int j = 0; j < 8; j++) {
            const int n = n0 + wn * 64 + j * 8 + t * 2;
            const float2 bb = *(const float2*)&bias[n];
#pragma unroll
            for (int h2 = 0; h2 < 2; h2++) {
                const int m = m0 + wm * 32 + i * 16 + g + h2 * 8;
                float2 v;
                v.x = acc[i][j][h2 * 2 + 0] + bb.x;
                v.y = acc[i][j][h2 * 2 + 1] + bb.y;
                if (MODE == 0) {
                    int bidx = m >> 10, tt = m & 1023;
                    int hh = n >> 6, d = n & 63;
                    *(float2*)&out[(((size_t)(bidx * HH + hh) << 10) + tt) * DHX + d] = v;
                } else {
                    *(float2*)&out[(size_t)m * DD + n] = v;
                }
            }
        }
    }
}

// ---------------------------------------------------------------------------
// Fused flash attention on tensor cores (tf32 mma).
// Block = (b, h, 64 q-rows). 128 threads = 4 warps; warp owns 16 q-rows.
// Q fragments register-resident; S and PV via m16n8k8; bias+mask folded in;
// online softmax in the mma accumulator layout; P round-trips through
// warp-private smem rows (syncwarp only).
// ---------------------------------------------------------------------------
#define KP 68   // Ks pitch (banks 4g+t distinct)
#define VP 72   // Vs pitch (banks 8t+g distinct)
#define PP 68   // Ps pitch

__global__ __launch_bounds__(128)
void attn_tc(const float* __restrict__ sp, const float* __restrict__ ed,
             const unsigned* __restrict__ mask)
{
    extern __shared__ unsigned smx[];
    unsigned* Ks = smx;                 // 64*KP
    unsigned* Vs = Ks + 64 * KP;        // 64*VP
    unsigned* Ps = Vs + 64 * VP;        // 64*PP (Q staging, then P tiles)

    const int tid  = threadIdx.x;
    const int lane = tid & 31;
    const int warp = tid >> 5;
    const int g = lane >> 2;
    const int t = lane & 3;
    const int q0 = blockIdx.x * 64;
    const int h  = blockIdx.y;
    const int b  = blockIdx.z;
    const int qb = warp * 16;

    const float* Qg = g_q + (size_t)(b * HH + h) * TT * DHX;
    const float* Kg = g_k + (size_t)(b * HH + h) * TT * DHX;
    const float* Vg = g_v + (size_t)(b * HH + h) * TT * DHX;

    // stage Q tile (64x64) into Ps as tf32
#pragma unroll
    for (int it = 0; it < 8; it++) {
        int idx = tid + it * 128;
        int r = idx >> 4, c4 = (idx & 15) << 2;
        float4 v = *(const float4*)&Qg[(size_t)(q0 + r) * DHX + c4];
        unsigned* p = &Ps[r * PP + c4];
        p[0] = f2tf(v.x); p[1] = f2tf(v.y); p[2] = f2tf(v.z); p[3] = f2tf(v.w);
    }
    __syncthreads();

    // Q fragments for all 8 k-steps (register resident)
    unsigned qf[8][4];
#pragma unroll
    for (int ks = 0; ks < 8; ks++) {
        qf[ks][0] = Ps[(qb + g) * PP + ks * 8 + t];
        qf[ks][1] = Ps[(qb + g + 8) * PP + ks * 8 + t];
        qf[ks][2] = Ps[(qb + g) * PP + ks * 8 + t + 4];
        qf[ks][3] = Ps[(qb + g + 8) * PP + ks * 8 + t + 4];
    }

    float o[8][4];
#pragma unroll
    for (int j = 0; j < 8; j++)
#pragma unroll
        for (int c = 0; c < 4; c++) o[j][c] = 0.0f;
    float m_run[2] = {-3e38f, -3e38f};
    float l_run[2] = {0.0f, 0.0f};

    for (int kt = 0; kt < 16; kt++) {
        const int k0 = kt * 64;
        __syncthreads();  // prior iter's mma reads of Ks/Vs done before overwrite

        // load K,V tiles (tf32)
#pragma unroll
        for (int it = 0; it < 8; it++) {
            int idx = tid + it * 128;
            int r = idx >> 4, c4 = (idx & 15) << 2;
            float4 kv = *(const float4*)&Kg[(size_t)(k0 + r) * DHX + c4];
            float4 vv = *(const float4*)&Vg[(size_t)(k0 + r) * DHX + c4];
            unsigned* pk = &Ks[r * KP + c4];
            pk[0] = f2tf(kv.x); pk[1] = f2tf(kv.y); pk[2] = f2tf(kv.z); pk[3] = f2tf(kv.w);
            unsigned* pv = &Vs[r * VP + c4];
            pv[0] = f2tf(vv.x); pv[1] = f2tf(vv.y); pv[2] = f2tf(vv.z); pv[3] = f2tf(vv.w);
        }
        __syncthreads();

        // S = Q K^T  (64 mma)
        float s[8][4];
#pragma unroll
        for (int j = 0; j < 8; j++)
#pragma unroll
            for (int c = 0; c < 4; c++) s[j][c] = 0.0f;

#pragma unroll
        for (int ks = 0; ks < 8; ks++) {
            unsigned bf[8][2];
#pragma unroll
            for (int j = 0; j < 8; j++) {
                bf[j][0] = Ks[(j * 8 + g) * KP + ks * 8 + t];
                bf[j][1] = Ks[(j * 8 + g) * KP + ks * 8 + t + 4];
            }
#pragma unroll
            for (int j = 0; j < 8; j++)
                mma8(s[j][0], s[j][1], s[j][2], s[j][3],
                     qf[ks][0], qf[ks][1], qf[ks][2], qf[ks][3],
                     bf[j][0], bf[j][1]);
        }

        // scale + bias + mask
#pragma unroll
        for (int j = 0; j < 8; j++) {
            const int kk = k0 + j * 8 + t * 2;
            uint2 mk = *(const uint2*)&mask[b * TT + kk];
            size_t base0 = ((size_t)b * TT + (q0 + qb + g)) * TT + kk;
            size_t base1 = base0 + (size_t)8 * TT;
            float2 s0 = *(const float2*)&sp[base0];
            float2 e0 = *(const float2*)&ed[base0];
            float2 s1 = *(const float2*)&sp[base1];
            float2 e1 = *(const float2*)&ed[base1];
            float b00 = mk.x ? -1e30f : (s0.x + e0.x);
            float b01 = mk.y ? -1e30f : (s0.y + e0.y);
            float b10 = mk.x ? -1e30f : (s1.x + e1.x);
            float b11 = mk.y ? -1e30f : (s1.y + e1.y);
            s[j][0] = s[j][0] * 0.125f + b00;
            s[j][1] = s[j][1] * 0.125f + b01;
            s[j][2] = s[j][2] * 0.125f + b10;
            s[j][3] = s[j][3] * 0.125f + b11;
        }

        // online softmax (rows g and g+8; row spread over quad lanes)
#pragma unroll
        for (int r = 0; r < 2; r++) {
            float mt = -3e38f;
#pragma unroll
            for (int j = 0; j < 8; j++)
                mt = fmaxf(mt, fmaxf(s[j][2 * r], s[j][2 * r + 1]));
            mt = fmaxf(mt, __shfl_xor_sync(0xffffffffu, mt, 1));
            mt = fmaxf(mt, __shfl_xor_sync(0xffffffffu, mt, 2));
            float m_new = fmaxf(m_run[r], mt);
            float alpha = __expf(m_run[r] - m_new);
            m_run[r] = m_new;
            float ls = 0.0f;
#pragma unroll
            for (int j = 0; j < 8; j++) {
                float p0 = __expf(s[j][2 * r] - m_new);
                float p1 = __expf(s[j][2 * r + 1] - m_new);
                s[j][2 * r] = p0; s[j][2 * r + 1] = p1;
                ls += p0 + p1;
            }
            ls += __shfl_xor_sync(0xffffffffu, ls, 1);
            ls += __shfl_xor_sync(0xffffffffu, ls, 2);
            l_run[r] = l_run[r] * alpha + ls;
#pragma unroll
            for (int j = 0; j < 8; j++) {
                o[j][2 * r] *= alpha;
                o[j][2 * r + 1] *= alpha;
            }
        }

        // P -> smem (warp-private rows), tf32
#pragma unroll
        for (int j = 0; j < 8; j++) {
            const int col = j * 8 + t * 2;
            unsigned* p0 = &Ps[(qb + g) * PP + col];
            p0[0] = f2tf(s[j][0]); p0[1] = f2tf(s[j][1]);
            unsigned* p1 = &Ps[(qb + g + 8) * PP + col];
            p1[0] = f2tf(s[j][2]); p1[1] = f2tf(s[j][3]);
        }
        __syncwarp();

        // O += P @ V  (64 mma)
#pragma unroll
        for (int kv = 0; kv < 8; kv++) {
            unsigned pa[4];
            pa[0] = Ps[(qb + g) * PP + kv * 8 + t];
            pa[1] = Ps[(qb + g + 8) * PP + kv * 8 + t];
            pa[2] = Ps[(qb + g) * PP + kv * 8 + t + 4];
            pa[3] = Ps[(qb + g + 8) * PP + kv * 8 + t + 4];
#pragma unroll
            for (int j = 0; j < 8; j++) {
                unsigned b0 = Vs[(kv * 8 + t) * VP + j * 8 + g];
                unsigned b1 = Vs[(kv * 8 + t + 4) * VP + j * 8 + g];
                mma8(o[j][0], o[j][1], o[j][2], o[j][3],
                     pa[0], pa[1], pa[2], pa[3], b0, b1);
            }
        }
    }

    // normalize + write (B,T,D)
    const float inv0 = 1.0f / l_run[0];
    const float inv1 = 1.0f / l_run[1];
#pragma unroll
    for (int j = 0; j < 8; j++) {
        const int d = h * DHX + j * 8 + t * 2;
        size_t r0 = ((size_t)b * TT + q0 + qb + g) * DD + d;
        size_t r1 = r0 + (size_t)8 * DD;
        float2 v0 = make_float2(o[j][0] * inv0, o[j][1] * inv0);
        float2 v1 = make_float2(o[j][2] * inv1, o[j][3] * inv1);
        *(float2*)&g_ctx[r0] = v0;
        *(float2*)&g_ctx[r1] = v1;
    }
}

// ---------------------------------------------------------------------------
// kernel_launch
// ---------------------------------------------------------------------------
extern "C" void kernel_launch(void* const* d_in, const int* in_sizes, int n_in,
                              void* d_out, int out_size)
{
    const float* query = (const float*)d_in[0];
    const float* key_  = (const float*)d_in[1];
    const float* value = (const float*)d_in[2];
    const float* sp    = (const float*)d_in[3];
    const float* edg   = (const float*)d_in[4];
    const unsigned int* mask = (const unsigned int*)d_in[5];
    const float* Wq = (const float*)d_in[6];
    const float* bq = (const float*)d_in[7];
    const float* Wk = (const float*)d_in[8];
    const float* bk = (const float*)d_in[9];
    const float* Wv = (const float*)d_in[10];
    const float* bv = (const float*)d_in[11];
    const float* Wo = (const float*)d_in[12];
    const float* bo = (const float*)d_in[13];
    float* out = (float*)d_out;

    float* gq;   cudaGetSymbolAddress((void**)&gq, g_q);
    float* gk;   cudaGetSymbolAddress((void**)&gk, g_k);
    float* gv;   cudaGetSymbolAddress((void**)&gv, g_v);
    float* gctx; cudaGetSymbolAddress((void**)&gctx, g_ctx);

    dim3 gemm_grid(DD / 128, MROWS / 128);  // (8, 64)
    gemm_tc<0><<<gemm_grid, 256>>>(query, Wq, bq, gq);
    gemm_tc<0><<<gemm_grid, 256>>>(key_,  Wk, bk, gk);
    gemm_tc<0><<<gemm_grid, 256>>>(value, Wv, bv, gv);

    const int attn_smem = (64 * KP + 64 * VP + 64 * PP) * (int)sizeof(unsigned);  // 53248
    cudaFuncSetAttribute(attn_tc, cudaFuncAttributeMaxDynamicSharedMemorySize, attn_smem);
    dim3 attn_grid(TT / 64, HH, BB);  // (16, 16, 8)
    attn_tc<<<attn_grid, 128, attn_smem>>>(sp, edg, mask);

    gemm_tc<1><<<gemm_grid, 256>>>(gctx, Wo, bo, out);
}

// round 6
// speedup vs baseline: 3.8019x; 1.0802x over previous
#include <cuda_runtime.h>
#include <cstdint>
#include <math.h>

// Problem constants
#define BB 8
#define TT 1024
#define DD 1024
#define HH 16
#define DHX 64
#define MROWS (BB*TT)   // 8192

// Scratch
__device__ float g_q[MROWS * DD];     // (B,H,T,DH)
__device__ float g_k[MROWS * DD];     // (B,H,T,DH)
__device__ float g_v[MROWS * DD];     // (B,H,T,DH)
__device__ float g_ctx[MROWS * DD];   // (B,T,D)
__device__ float g_bias[BB * TT * TT]; // fused masked bias (B,T,T)

// ---------------------------------------------------------------------------
// helpers
// ---------------------------------------------------------------------------
__device__ __forceinline__ unsigned f2tf(float f) {
    unsigned u;
    asm("cvt.rna.tf32.f32 %0, %1;" : "=r"(u) : "f"(f));
    return u;
}
__device__ __forceinline__ void mma8(float& c0, float& c1, float& c2, float& c3,
                                     unsigned a0, unsigned a1, unsigned a2, unsigned a3,
                                     unsigned b0, unsigned b1) {
    asm("mma.sync.aligned.m16n8k8.row.col.f32.tf32.tf32.f32 "
        "{%0,%1,%2,%3}, {%4,%5,%6,%7}, {%8,%9}, {%0,%1,%2,%3};"
        : "+f"(c0), "+f"(c1), "+f"(c2), "+f"(c3)
        : "r"(a0), "r"(a1), "r"(a2), "r"(a3), "r"(b0), "r"(b1));
}

// ---------------------------------------------------------------------------
// bias pre-fusion: g_bias = mask ? -1e30 : sp + ed   (float4 elementwise)
// ---------------------------------------------------------------------------
__global__ __launch_bounds__(256)
void bias_fuse(const float4* __restrict__ sp4, const float4* __restrict__ ed4,
               const unsigned* __restrict__ mask, float4* __restrict__ out4)
{
    const int idx = blockIdx.x * 256 + threadIdx.x;       // float4 index
    const int b = idx >> 18;                               // / (T*T/4)
    const int e4 = idx & 262143;
    const int col = (e4 & 255) << 2;
    const uint4 mk = *(const uint4*)&mask[b * TT + col];
    const float4 s = sp4[idx];
    const float4 e = ed4[idx];
    float4 o;
    o.x = mk.x ? -1e30f : (s.x + e.x);
    o.y = mk.y ? -1e30f : (s.y + e.y);
    o.z = mk.z ? -1e30f : (s.z + e.z);
    o.w = mk.w ? -1e30f : (s.w + e.w);
    out4[idx] = o;
}

// ---------------------------------------------------------------------------
// tf32 tensor-core GEMM (R4, proven): C[8192,1024] = A @ W + bias
// BM=128 BN=128 BK=16, 256 threads = 8 warps (4m x 2n), warp tile 32x64.
// MODE 0: scatter to (B,H,T,DH); MODE 1: row-major.
// ---------------------------------------------------------------------------
#define GPA 20
#define GPW 136

template<int MODE>
__global__ __launch_bounds__(256, 2)
void gemm_tc(const float* __restrict__ A, const float* __restrict__ W,
             const float* __restrict__ bias, float* __restrict__ out)
{
    __shared__ unsigned As[2][128 * GPA];
    __shared__ unsigned Ws[2][16 * GPW];

    const int tid  = threadIdx.x;
    const int lane = tid & 31;
    const int warp = tid >> 5;
    const int g = lane >> 2;
    const int t = lane & 3;
    const int wm = warp >> 1;
    const int wn = warp & 1;
    const int m0 = blockIdx.y * 128;
    const int n0 = blockIdx.x * 128;

    float4 ra[2], rw[2];

#pragma unroll
    for (int it = 0; it < 2; it++) {
        int idx = tid + it * 256;
        ra[it] = *(const float4*)&A[(size_t)(m0 + (idx >> 2)) * DD + ((idx & 3) << 2)];
        rw[it] = *(const float4*)&W[(size_t)(idx >> 5) * DD + n0 + ((idx & 31) << 2)];
    }
#pragma unroll
    for (int it = 0; it < 2; it++) {
        int idx = tid + it * 256;
        unsigned* pa = &As[0][(idx >> 2) * GPA + ((idx & 3) << 2)];
        pa[0] = f2tf(ra[it].x); pa[1] = f2tf(ra[it].y); pa[2] = f2tf(ra[it].z); pa[3] = f2tf(ra[it].w);
        unsigned* pw = &Ws[0][(idx >> 5) * GPW + ((idx & 31) << 2)];
        pw[0] = f2tf(rw[it].x); pw[1] = f2tf(rw[it].y); pw[2] = f2tf(rw[it].z); pw[3] = f2tf(rw[it].w);
    }
    __syncthreads();

    float acc[2][8][4];
#pragma unroll
    for (int i = 0; i < 2; i++)
#pragma unroll
        for (int j = 0; j < 8; j++)
#pragma unroll
            for (int c = 0; c < 4; c++) acc[i][j][c] = 0.0f;

    for (int kt = 0; kt < 64; kt++) {
        const int cur = kt & 1;
        if (kt + 1 < 64) {
            const int k0 = (kt + 1) * 16;
#pragma unroll
            for (int it = 0; it < 2; it++) {
                int idx = tid + it * 256;
                ra[it] = *(const float4*)&A[(size_t)(m0 + (idx >> 2)) * DD + k0 + ((idx & 3) << 2)];
                rw[it] = *(const float4*)&W[(size_t)(k0 + (idx >> 5)) * DD + n0 + ((idx & 31) << 2)];
            }
        }

#pragma unroll
        for (int ks = 0; ks < 16; ks += 8) {
            unsigned af[2][4], bf[8][2];
#pragma unroll
            for (int i = 0; i < 2; i++) {
                int mb = wm * 32 + i * 16;
                af[i][0] = As[cur][(mb + g) * GPA + ks + t];
                af[i][1] = As[cur][(mb + g + 8) * GPA + ks + t];
                af[i][2] = As[cur][(mb + g) * GPA + ks + t + 4];
                af[i][3] = As[cur][(mb + g + 8) * GPA + ks + t + 4];
            }
#pragma unroll
            for (int j = 0; j < 8; j++) {
                int nb = wn * 64 + j * 8;
                bf[j][0] = Ws[cur][(ks + t) * GPW + nb + g];
                bf[j][1] = Ws[cur][(ks + t + 4) * GPW + nb + g];
            }
#pragma unroll
            for (int i = 0; i < 2; i++)
#pragma unroll
                for (int j = 0; j < 8; j++)
                    mma8(acc[i][j][0], acc[i][j][1], acc[i][j][2], acc[i][j][3],
                         af[i][0], af[i][1], af[i][2], af[i][3],
                         bf[j][0], bf[j][1]);
        }

        if (kt + 1 < 64) {
            const int nxt = (kt + 1) & 1;
#pragma unroll
            for (int it = 0; it < 2; it++) {
                int idx = tid + it * 256;
                unsigned* pa = &As[nxt][(idx >> 2) * GPA + ((idx & 3) << 2)];
                pa[0] = f2tf(ra[it].x); pa[1] = f2tf(ra[it].y); pa[2] = f2tf(ra[it].z); pa[3] = f2tf(ra[it].w);
                unsigned* pw = &Ws[nxt][(idx >> 5) * GPW + ((idx & 31) << 2)];
                pw[0] = f2tf(rw[it].x); pw[1] = f2tf(rw[it].y); pw[2] = f2tf(rw[it].z); pw[3] = f2tf(rw[it].w);
            }
        }
        __syncthreads();
    }

#pragma unroll
    for (int i = 0; i < 2; i++) {
#pragma unroll
        for (int j = 0; j < 8; j++) {
            const int n = n0 + wn * 64 + j * 8 + t * 2;
            const float2 bb = *(const float2*)&bias[n];
#pragma unroll
            for (int h2 = 0; h2 < 2; h2++) {
                const int m = m0 + wm * 32 + i * 16 + g + h2 * 8;
                float2 v;
                v.x = acc[i][j][h2 * 2 + 0] + bb.x;
                v.y = acc[i][j][h2 * 2 + 1] + bb.y;
                if (MODE == 0) {
                    int bidx = m >> 10, tt = m & 1023;
                    int hh = n >> 6, d = n & 63;
                    *(float2*)&out[(((size_t)(bidx * HH + hh) << 10) + tt) * DHX + d] = v;
                } else {
                    *(float2*)&out[(size_t)m * DD + n] = v;
                }
            }
        }
    }
}

// ---------------------------------------------------------------------------
// Fused flash attention v2 (tf32 mma.sync).
// Block = (b, h, 128 q-rows). 128 threads = 4 warps; warp owns 32 q-rows
// (2 x m16 tiles). K/V fragments loaded once per k-step and shared across
// both m-tiles -> ~1.67x fewer LDS per FLOP than R4. Bias read from
// pre-fused g_bias. P round-trips via warp-private smem rows.
// ---------------------------------------------------------------------------
#define KP 68
#define VP 72
#define PP 68
#define ATTN_SMEM ((64*KP + 64*VP + 128*PP) * 4)   // 70656 bytes

__global__ __launch_bounds__(128)
void attn_tc2(const float* __restrict__ gb)
{
    extern __shared__ unsigned smx[];
    unsigned* Ks = smx;                 // 64 x KP
    unsigned* Vs = Ks + 64 * KP;        // 64 x VP
    unsigned* Ps = Vs + 64 * VP;        // 128 x PP (Q staging, then P)

    const int tid  = threadIdx.x;
    const int lane = tid & 31;
    const int warp = tid >> 5;
    const int g = lane >> 2;
    const int t = lane & 3;
    const int q0 = blockIdx.x * 128;
    const int h  = blockIdx.y;
    const int b  = blockIdx.z;
    const int qb = warp * 32;

    const float* Qg = g_q + (size_t)(b * HH + h) * TT * DHX;
    const float* Kg = g_k + (size_t)(b * HH + h) * TT * DHX;
    const float* Vg = g_v + (size_t)(b * HH + h) * TT * DHX;

    // stage Q tile (128x64) into Ps as tf32
#pragma unroll
    for (int it = 0; it < 16; it++) {
        int idx = tid + it * 128;
        int r = idx >> 4, c4 = (idx & 15) << 2;
        float4 v = *(const float4*)&Qg[(size_t)(q0 + r) * DHX + c4];
        unsigned* p = &Ps[r * PP + c4];
        p[0] = f2tf(v.x); p[1] = f2tf(v.y); p[2] = f2tf(v.z); p[3] = f2tf(v.w);
    }
    __syncthreads();

    // Q fragments, 2 m-tiles x 8 k-steps, register resident
    unsigned qf[2][8][4];
#pragma unroll
    for (int mt = 0; mt < 2; mt++)
#pragma unroll
        for (int ks = 0; ks < 8; ks++) {
            const int r0 = (qb + mt * 16 + g) * PP + ks * 8 + t;
            qf[mt][ks][0] = Ps[r0];
            qf[mt][ks][1] = Ps[r0 + 8 * PP];
            qf[mt][ks][2] = Ps[r0 + 4];
            qf[mt][ks][3] = Ps[r0 + 8 * PP + 4];
        }

    float o[2][8][4];
#pragma unroll
    for (int mt = 0; mt < 2; mt++)
#pragma unroll
        for (int j = 0; j < 8; j++)
#pragma unroll
            for (int c = 0; c < 4; c++) o[mt][j][c] = 0.0f;
    float m_run[2][2] = {{-3e38f, -3e38f}, {-3e38f, -3e38f}};
    float l_run[2][2] = {{0.0f, 0.0f}, {0.0f, 0.0f}};

    for (int kt = 0; kt < 16; kt++) {
        const int k0 = kt * 64;
        __syncthreads();   // prior iter's K/V reads done

        // load K,V tiles (tf32)
#pragma unroll
        for (int it = 0; it < 8; it++) {
            int idx = tid + it * 128;
            int r = idx >> 4, c4 = (idx & 15) << 2;
            float4 kv = *(const float4*)&Kg[(size_t)(k0 + r) * DHX + c4];
            float4 vv = *(const float4*)&Vg[(size_t)(k0 + r) * DHX + c4];
            unsigned* pk = &Ks[r * KP + c4];
            pk[0] = f2tf(kv.x); pk[1] = f2tf(kv.y); pk[2] = f2tf(kv.z); pk[3] = f2tf(kv.w);
            unsigned* pv = &Vs[r * VP + c4];
            pv[0] = f2tf(vv.x); pv[1] = f2tf(vv.y); pv[2] = f2tf(vv.z); pv[3] = f2tf(vv.w);
        }
        __syncthreads();

        // S = Q K^T : K fragments shared across both m-tiles
        float s[2][8][4];
#pragma unroll
        for (int mt = 0; mt < 2; mt++)
#pragma unroll
            for (int j = 0; j < 8; j++)
#pragma unroll
                for (int c = 0; c < 4; c++) s[mt][j][c] = 0.0f;

#pragma unroll
        for (int ks = 0; ks < 8; ks++) {
            unsigned kf[8][2];
#pragma unroll
            for (int j = 0; j < 8; j++) {
                kf[j][0] = Ks[(j * 8 + g) * KP + ks * 8 + t];
                kf[j][1] = Ks[(j * 8 + g) * KP + ks * 8 + t + 4];
            }
#pragma unroll
            for (int mt = 0; mt < 2; mt++)
#pragma unroll
                for (int j = 0; j < 8; j++)
                    mma8(s[mt][j][0], s[mt][j][1], s[mt][j][2], s[mt][j][3],
                         qf[mt][ks][0], qf[mt][ks][1], qf[mt][ks][2], qf[mt][ks][3],
                         kf[j][0], kf[j][1]);
        }

        // scale + fused bias
#pragma unroll
        for (int mt = 0; mt < 2; mt++)
#pragma unroll
            for (int j = 0; j < 8; j++) {
                const int col = k0 + j * 8 + t * 2;
                const size_t i0 = ((size_t)b * TT + (q0 + qb + mt * 16 + g)) * TT + col;
                float2 b0 = *(const float2*)&gb[i0];
                float2 b1 = *(const float2*)&gb[i0 + (size_t)8 * TT];
                s[mt][j][0] = s[mt][j][0] * 0.125f + b0.x;
                s[mt][j][1] = s[mt][j][1] * 0.125f + b0.y;
                s[mt][j][2] = s[mt][j][2] * 0.125f + b1.x;
                s[mt][j][3] = s[mt][j][3] * 0.125f + b1.y;
            }

        // online softmax
#pragma unroll
        for (int mt = 0; mt < 2; mt++)
#pragma unroll
            for (int r = 0; r < 2; r++) {
                float mt_ = -3e38f;
#pragma unroll
                for (int j = 0; j < 8; j++)
                    mt_ = fmaxf(mt_, fmaxf(s[mt][j][2 * r], s[mt][j][2 * r + 1]));
                mt_ = fmaxf(mt_, __shfl_xor_sync(0xffffffffu, mt_, 1));
                mt_ = fmaxf(mt_, __shfl_xor_sync(0xffffffffu, mt_, 2));
                float m_new = fmaxf(m_run[mt][r], mt_);
                float alpha = __expf(m_run[mt][r] - m_new);
                m_run[mt][r] = m_new;
                float ls = 0.0f;
#pragma unroll
                for (int j = 0; j < 8; j++) {
                    float p0 = __expf(s[mt][j][2 * r] - m_new);
                    float p1 = __expf(s[mt][j][2 * r + 1] - m_new);
                    s[mt][j][2 * r] = p0; s[mt][j][2 * r + 1] = p1;
                    ls += p0 + p1;
                }
                ls += __shfl_xor_sync(0xffffffffu, ls, 1);
                ls += __shfl_xor_sync(0xffffffffu, ls, 2);
                l_run[mt][r] = l_run[mt][r] * alpha + ls;
#pragma unroll
                for (int j = 0; j < 8; j++) {
                    o[mt][j][2 * r] *= alpha;
                    o[mt][j][2 * r + 1] *= alpha;
                }
            }

        // P -> smem (warp-private rows), packed uint2 stores
#pragma unroll
        for (int mt = 0; mt < 2; mt++)
#pragma unroll
            for (int j = 0; j < 8; j++) {
                const int col = j * 8 + t * 2;
                const int r0 = (qb + mt * 16 + g) * PP + col;
                uint2 v0 = make_uint2(f2tf(s[mt][j][0]), f2tf(s[mt][j][1]));
                uint2 v1 = make_uint2(f2tf(s[mt][j][2]), f2tf(s[mt][j][3]));
                *(uint2*)&Ps[r0] = v0;
                *(uint2*)&Ps[r0 + 8 * PP] = v1;
            }
        __syncwarp();

        // O += P @ V : V fragments shared across both m-tiles
#pragma unroll
        for (int kv = 0; kv < 8; kv++) {
            unsigned vb[8][2];
#pragma unroll
            for (int j = 0; j < 8; j++) {
                vb[j][0] = Vs[(kv * 8 + t) * VP + j * 8 + g];
                vb[j][1] = Vs[(kv * 8 + t + 4) * VP + j * 8 + g];
            }
#pragma unroll
            for (int mt = 0; mt < 2; mt++) {
                unsigned pa[4];
                const int r0 = (qb + mt * 16 + g) * PP + kv * 8 + t;
                pa[0] = Ps[r0];
                pa[1] = Ps[r0 + 8 * PP];
                pa[2] = Ps[r0 + 4];
                pa[3] = Ps[r0 + 8 * PP + 4];
#pragma unroll
                for (int j = 0; j < 8; j++)
                    mma8(o[mt][j][0], o[mt][j][1], o[mt][j][2], o[mt][j][3],
                         pa[0], pa[1], pa[2], pa[3], vb[j][0], vb[j][1]);
            }
        }
    }

    // normalize + write (B,T,D)
#pragma unroll
    for (int mt = 0; mt < 2; mt++) {
        const float inv0 = 1.0f / l_run[mt][0];
        const float inv1 = 1.0f / l_run[mt][1];
#pragma unroll
        for (int j = 0; j < 8; j++) {
            const int d = h * DHX + j * 8 + t * 2;
            size_t r0 = ((size_t)b * TT + q0 + qb + mt * 16 + g) * DD + d;
            size_t r1 = r0 + (size_t)8 * DD;
            float2 v0 = make_float2(o[mt][j][0] * inv0, o[mt][j][1] * inv0);
            float2 v1 = make_float2(o[mt][j][2] * inv1, o[mt][j][3] * inv1);
            *(float2*)&g_ctx[r0] = v0;
            *(float2*)&g_ctx[r1] = v1;
        }
    }
}

// ---------------------------------------------------------------------------
// kernel_launch
// ---------------------------------------------------------------------------
extern "C" void kernel_launch(void* const* d_in, const int* in_sizes, int n_in,
                              void* d_out, int out_size)
{
    const float* query = (const float*)d_in[0];
    const float* key_  = (const float*)d_in[1];
    const float* value = (const float*)d_in[2];
    const float* sp    = (const float*)d_in[3];
    const float* edg   = (const float*)d_in[4];
    const unsigned int* mask = (const unsigned int*)d_in[5];
    const float* Wq = (const float*)d_in[6];
    const float* bq = (const float*)d_in[7];
    const float* Wk = (const float*)d_in[8];
    const float* bk = (const float*)d_in[9];
    const float* Wv = (const float*)d_in[10];
    const float* bv = (const float*)d_in[11];
    const float* Wo = (const float*)d_in[12];
    const float* bo = (const float*)d_in[13];
    float* out = (float*)d_out;

    float* gq;   cudaGetSymbolAddress((void**)&gq, g_q);
    float* gk;   cudaGetSymbolAddress((void**)&gk, g_k);
    float* gv;   cudaGetSymbolAddress((void**)&gv, g_v);
    float* gctx; cudaGetSymbolAddress((void**)&gctx, g_ctx);
    float* gb;   cudaGetSymbolAddress((void**)&gb, g_bias);

    // fused masked bias (independent of GEMMs)
    bias_fuse<<<BB * TT * TT / 4 / 256, 256>>>((const float4*)sp, (const float4*)edg,
                                               mask, (float4*)gb);

    dim3 gemm_grid(DD / 128, MROWS / 128);  // (8, 64)
    gemm_tc<0><<<gemm_grid, 256>>>(query, Wq, bq, gq);
    gemm_tc<0><<<gemm_grid, 256>>>(key_,  Wk, bk, gk);
    gemm_tc<0><<<gemm_grid, 256>>>(value, Wv, bv, gv);

    cudaFuncSetAttribute(attn_tc2, cudaFuncAttributeMaxDynamicSharedMemorySize, ATTN_SMEM);
    dim3 attn_grid(TT / 128, HH, BB);  // (8, 16, 8)
    attn_tc2<<<attn_grid, 128, ATTN_SMEM>>>(gb);

    gemm_tc<1><<<gemm_grid, 256>>>(gctx, Wo, bo, out);
}

// round 7
// speedup vs baseline: 3.8668x; 1.0171x over previous
#include <cuda_runtime.h>
#include <cstdint>
#include <math.h>

// Problem constants
#define BB 8
#define TT 1024
#define DD 1024
#define HH 16
#define DHX 64
#define MROWS (BB*TT)   // 8192

// Scratch
__device__ float g_q[MROWS * DD];     // (B,H,T,DH)
__device__ float g_k[MROWS * DD];     // (B,H,T,DH)
__device__ float g_v[MROWS * DD];     // (B,H,T,DH)
__device__ float g_ctx[MROWS * DD];   // (B,T,D)
__device__ float g_bias[BB * TT * TT]; // fused masked bias (B,T,T)

// ---------------------------------------------------------------------------
// helpers
// ---------------------------------------------------------------------------
__device__ __forceinline__ unsigned f2tf(float f) {
    unsigned u;
    asm("cvt.rna.tf32.f32 %0, %1;" : "=r"(u) : "f"(f));
    return u;
}
__device__ __forceinline__ void mma8(float& c0, float& c1, float& c2, float& c3,
                                     unsigned a0, unsigned a1, unsigned a2, unsigned a3,
                                     unsigned b0, unsigned b1) {
    asm("mma.sync.aligned.m16n8k8.row.col.f32.tf32.tf32.f32 "
        "{%0,%1,%2,%3}, {%4,%5,%6,%7}, {%8,%9}, {%0,%1,%2,%3};"
        : "+f"(c0), "+f"(c1), "+f"(c2), "+f"(c3)
        : "r"(a0), "r"(a1), "r"(a2), "r"(a3), "r"(b0), "r"(b1));
}
__device__ __forceinline__ uint32_t smem_u32(const void* p) {
    uint32_t a;
    asm("{ .reg .u64 t; cvta.to.shared.u64 t, %1; cvt.u32.u64 %0, t; }" : "=r"(a) : "l"(p));
    return a;
}
#define CP16(dst, src) \
    asm volatile("cp.async.cg.shared.global [%0], [%1], 16;" :: "r"(dst), "l"(src))
#define CP_COMMIT() asm volatile("cp.async.commit_group;" ::: "memory")
#define CP_WAIT1()  asm volatile("cp.async.wait_group 1;" ::: "memory")

// ---------------------------------------------------------------------------
// bias pre-fusion: g_bias = mask ? -1e30 : sp + ed
// ---------------------------------------------------------------------------
__global__ __launch_bounds__(256)
void bias_fuse(const float4* __restrict__ sp4, const float4* __restrict__ ed4,
               const unsigned* __restrict__ mask, float4* __restrict__ out4)
{
    const int idx = blockIdx.x * 256 + threadIdx.x;
    const int b = idx >> 18;
    const int e4 = idx & 262143;
    const int col = (e4 & 255) << 2;
    const uint4 mk = *(const uint4*)&mask[b * TT + col];
    const float4 s = sp4[idx];
    const float4 e = ed4[idx];
    float4 o;
    o.x = mk.x ? -1e30f : (s.x + e.x);
    o.y = mk.y ? -1e30f : (s.y + e.y);
    o.z = mk.z ? -1e30f : (s.z + e.z);
    o.w = mk.w ? -1e30f : (s.w + e.w);
    out4[idx] = o;
}

// ---------------------------------------------------------------------------
// cp.async multistage tf32 GEMM: C[8192,1024] = A @ W + bias
// BM=128 BN=128 BK=32, 3 stages, 256 threads = 8 warps (4m x 2n).
// smem holds raw fp32; cvt.rna.tf32 applied after LDS at fragment load
// (bit-identical numerics to converting at STS time).
// A pitch 36 floats (144B, 16B-multiple; bank 4g+t conflict-free)
// B pitch 136 floats (544B, 16B-multiple; bank 8t+g conflict-free)
// MODE 0: QKV fused via blockIdx.z, scatter to (B,H,T,DH). MODE 1: row-major.
// ---------------------------------------------------------------------------
#define APF 36
#define BPF 136
#define ASTAGE (128 * APF)          // floats per A stage
#define BSTAGE (32 * BPF)           // floats per B stage
#define GSMEM ((3 * (ASTAGE + BSTAGE)) * 4)   // 107520 bytes

template<int MODE>
__global__ __launch_bounds__(256, 2)
void gemm_cp(const float* __restrict__ A0, const float* __restrict__ A1, const float* __restrict__ A2,
             const float* __restrict__ W0, const float* __restrict__ W1, const float* __restrict__ W2,
             const float* __restrict__ bp0, const float* __restrict__ bp1, const float* __restrict__ bp2,
             float* __restrict__ O0, float* __restrict__ O1, float* __restrict__ O2)
{
    extern __shared__ __align__(16) float smf[];
    float* As[3] = { smf, smf + ASTAGE, smf + 2 * ASTAGE };
    float* Bs[3] = { smf + 3 * ASTAGE, smf + 3 * ASTAGE + BSTAGE, smf + 3 * ASTAGE + 2 * BSTAGE };

    const int tid  = threadIdx.x;
    const int lane = tid & 31;
    const int warp = tid >> 5;
    const int g = lane >> 2;
    const int t = lane & 3;
    const int wm = warp >> 1;
    const int wn = warp & 1;
    const int m0 = blockIdx.y * 128;
    const int n0 = blockIdx.x * 128;

    const float* A = A0; const float* W = W0; const float* bias = bp0; float* out = O0;
    if (MODE == 0) {
        if (blockIdx.z == 1) { A = A1; W = W1; bias = bp1; out = O1; }
        else if (blockIdx.z == 2) { A = A2; W = W2; bias = bp2; out = O2; }
    }

    // per-thread cp.async assignments (4 chunks A + 4 chunks B per stage)
    const int am = tid >> 1;                 // A: threads cover 128 rows x 8 chunks via 2 passes
    const int ac = (tid & 1) << 2;           //   pass p adds +0/+4 chunk offset? use explicit loop below
    (void)am; (void)ac;

    const uint32_t a_smem0 = smem_u32(As[0]);
    const uint32_t b_smem0 = smem_u32(Bs[0]);

    auto issue_stage = [&](int kt, int slot) {
        const int k0 = kt * 32;
        const uint32_t abase = a_smem0 + slot * ASTAGE * 4;
        const uint32_t bbase = b_smem0 + slot * BSTAGE * 4;
        // A: 128 rows x 8 chunks(16B) = 1024 chunks / 256 thr = 4 each
#pragma unroll
        for (int it = 0; it < 4; it++) {
            int idx = tid + it * 256;
            int m = idx >> 3, ch = idx & 7;
            CP16(abase + (uint32_t)(m * APF + ch * 4) * 4,
                 &A[(size_t)(m0 + m) * DD + k0 + ch * 4]);
        }
        // B: 32 rows x 32 chunks = 1024 chunks / 256 thr = 4 each
#pragma unroll
        for (int it = 0; it < 4; it++) {
            int idx = tid + it * 256;
            int kk = idx >> 5, nn = (idx & 31) << 2;
            CP16(bbase + (uint32_t)(kk * BPF + nn) * 4,
                 &W[(size_t)(k0 + kk) * DD + n0 + nn]);
        }
    };

    // prologue: stages 0,1
    issue_stage(0, 0); CP_COMMIT();
    issue_stage(1, 1); CP_COMMIT();

    float acc[2][8][4];
#pragma unroll
    for (int i = 0; i < 2; i++)
#pragma unroll
        for (int j = 0; j < 8; j++)
#pragma unroll
            for (int c = 0; c < 4; c++) acc[i][j][c] = 0.0f;

    for (int kt = 0; kt < 32; kt++) {
        CP_WAIT1();            // stage kt resident
        __syncthreads();       // visible to all; all threads done with slot (kt-1)%3

        if (kt + 2 < 32) issue_stage(kt + 2, (kt + 2) % 3);
        CP_COMMIT();           // commit every iter to keep group counting uniform

        const float* as = As[kt % 3];
        const float* bs = Bs[kt % 3];

#pragma unroll
        for (int ks = 0; ks < 32; ks += 8) {
            unsigned af[2][4], bf[8][2];
#pragma unroll
            for (int i = 0; i < 2; i++) {
                const int mb = wm * 32 + i * 16;
                af[i][0] = f2tf(as[(mb + g) * APF + ks + t]);
                af[i][1] = f2tf(as[(mb + g + 8) * APF + ks + t]);
                af[i][2] = f2tf(as[(mb + g) * APF + ks + t + 4]);
                af[i][3] = f2tf(as[(mb + g + 8) * APF + ks + t + 4]);
            }
#pragma unroll
            for (int j = 0; j < 8; j++) {
                const int nb = wn * 64 + j * 8;
                bf[j][0] = f2tf(bs[(ks + t) * BPF + nb + g]);
                bf[j][1] = f2tf(bs[(ks + t + 4) * BPF + nb + g]);
            }
#pragma unroll
            for (int i = 0; i < 2; i++)
#pragma unroll
                for (int j = 0; j < 8; j++)
                    mma8(acc[i][j][0], acc[i][j][1], acc[i][j][2], acc[i][j][3],
                         af[i][0], af[i][1], af[i][2], af[i][3],
                         bf[j][0], bf[j][1]);
        }
        __syncthreads();       // all reads of slot kt%3 done before it is refilled
    }

    // epilogue
#pragma unroll
    for (int i = 0; i < 2; i++) {
#pragma unroll
        for (int j = 0; j < 8; j++) {
            const int n = n0 + wn * 64 + j * 8 + t * 2;
            const float2 bb = *(const float2*)&bias[n];
#pragma unroll
            for (int h2 = 0; h2 < 2; h2++) {
                const int m = m0 + wm * 32 + i * 16 + g + h2 * 8;
                float2 v;
                v.x = acc[i][j][h2 * 2 + 0] + bb.x;
                v.y = acc[i][j][h2 * 2 + 1] + bb.y;
                if (MODE == 0) {
                    int bidx = m >> 10, tt = m & 1023;
                    int hh = n >> 6, d = n & 63;
                    *(float2*)&out[(((size_t)(bidx * HH + hh) << 10) + tt) * DHX + d] = v;
                } else {
                    *(float2*)&out[(size_t)m * DD + n] = v;
                }
            }
        }
    }
}

// ---------------------------------------------------------------------------
// Fused flash attention v2 (tf32 mma.sync) -- UNCHANGED from R6.
// ---------------------------------------------------------------------------
#define KP 68
#define VP 72
#define PP 68
#define ATTN_SMEM ((64*KP + 64*VP + 128*PP) * 4)   // 70656 bytes

__global__ __launch_bounds__(128)
void attn_tc2(const float* __restrict__ gb)
{
    extern __shared__ unsigned smx[];
    unsigned* Ks = smx;
    unsigned* Vs = Ks + 64 * KP;
    unsigned* Ps = Vs + 64 * VP;

    const int tid  = threadIdx.x;
    const int lane = tid & 31;
    const int warp = tid >> 5;
    const int g = lane >> 2;
    const int t = lane & 3;
    const int q0 = blockIdx.x * 128;
    const int h  = blockIdx.y;
    const int b  = blockIdx.z;
    const int qb = warp * 32;

    const float* Qg = g_q + (size_t)(b * HH + h) * TT * DHX;
    const float* Kg = g_k + (size_t)(b * HH + h) * TT * DHX;
    const float* Vg = g_v + (size_t)(b * HH + h) * TT * DHX;

#pragma unroll
    for (int it = 0; it < 16; it++) {
        int idx = tid + it * 128;
        int r = idx >> 4, c4 = (idx & 15) << 2;
        float4 v = *(const float4*)&Qg[(size_t)(q0 + r) * DHX + c4];
        unsigned* p = &Ps[r * PP + c4];
        p[0] = f2tf(v.x); p[1] = f2tf(v.y); p[2] = f2tf(v.z); p[3] = f2tf(v.w);
    }
    __syncthreads();

    unsigned qf[2][8][4];
#pragma unroll
    for (int mt = 0; mt < 2; mt++)
#pragma unroll
        for (int ks = 0; ks < 8; ks++) {
            const int r0 = (qb + mt * 16 + g) * PP + ks * 8 + t;
            qf[mt][ks][0] = Ps[r0];
            qf[mt][ks][1] = Ps[r0 + 8 * PP];
            qf[mt][ks][2] = Ps[r0 + 4];
            qf[mt][ks][3] = Ps[r0 + 8 * PP + 4];
        }

    float o[2][8][4];
#pragma unroll
    for (int mt = 0; mt < 2; mt++)
#pragma unroll
        for (int j = 0; j < 8; j++)
#pragma unroll
            for (int c = 0; c < 4; c++) o[mt][j][c] = 0.0f;
    float m_run[2][2] = {{-3e38f, -3e38f}, {-3e38f, -3e38f}};
    float l_run[2][2] = {{0.0f, 0.0f}, {0.0f, 0.0f}};

    for (int kt = 0; kt < 16; kt++) {
        const int k0 = kt * 64;
        __syncthreads();

#pragma unroll
        for (int it = 0; it < 8; it++) {
            int idx = tid + it * 128;
            int r = idx >> 4, c4 = (idx & 15) << 2;
            float4 kv = *(const float4*)&Kg[(size_t)(k0 + r) * DHX + c4];
            float4 vv = *(const float4*)&Vg[(size_t)(k0 + r) * DHX + c4];
            unsigned* pk = &Ks[r * KP + c4];
            pk[0] = f2tf(kv.x); pk[1] = f2tf(kv.y); pk[2] = f2tf(kv.z); pk[3] = f2tf(kv.w);
            unsigned* pv = &Vs[r * VP + c4];
            pv[0] = f2tf(vv.x); pv[1] = f2tf(vv.y); pv[2] = f2tf(vv.z); pv[3] = f2tf(vv.w);
        }
        __syncthreads();

        float s[2][8][4];
#pragma unroll
        for (int mt = 0; mt < 2; mt++)
#pragma unroll
            for (int j = 0; j < 8; j++)
#pragma unroll
                for (int c = 0; c < 4; c++) s[mt][j][c] = 0.0f;

#pragma unroll
        for (int ks = 0; ks < 8; ks++) {
            unsigned kf[8][2];
#pragma unroll
            for (int j = 0; j < 8; j++) {
                kf[j][0] = Ks[(j * 8 + g) * KP + ks * 8 + t];
                kf[j][1] = Ks[(j * 8 + g) * KP + ks * 8 + t + 4];
            }
#pragma unroll
            for (int mt = 0; mt < 2; mt++)
#pragma unroll
                for (int j = 0; j < 8; j++)
                    mma8(s[mt][j][0], s[mt][j][1], s[mt][j][2], s[mt][j][3],
                         qf[mt][ks][0], qf[mt][ks][1], qf[mt][ks][2], qf[mt][ks][3],
                         kf[j][0], kf[j][1]);
        }

#pragma unroll
        for (int mt = 0; mt < 2; mt++)
#pragma unroll
            for (int j = 0; j < 8; j++) {
                const int col = k0 + j * 8 + t * 2;
                const size_t i0 = ((size_t)b * TT + (q0 + qb + mt * 16 + g)) * TT + col;
                float2 b0 = *(const float2*)&gb[i0];
                float2 b1 = *(const float2*)&gb[i0 + (size_t)8 * TT];
                s[mt][j][0] = s[mt][j][0] * 0.125f + b0.x;
                s[mt][j][1] = s[mt][j][1] * 0.125f + b0.y;
                s[mt][j][2] = s[mt][j][2] * 0.125f + b1.x;
                s[mt][j][3] = s[mt][j][3] * 0.125f + b1.y;
            }

#pragma unroll
        for (int mt = 0; mt < 2; mt++)
#pragma unroll
            for (int r = 0; r < 2; r++) {
                float mt_ = -3e38f;
#pragma unroll
                for (int j = 0; j < 8; j++)
                    mt_ = fmaxf(mt_, fmaxf(s[mt][j][2 * r], s[mt][j][2 * r + 1]));
                mt_ = fmaxf(mt_, __shfl_xor_sync(0xffffffffu, mt_, 1));
                mt_ = fmaxf(mt_, __shfl_xor_sync(0xffffffffu, mt_, 2));
                float m_new = fmaxf(m_run[mt][r], mt_);
                float alpha = __expf(m_run[mt][r] - m_new);
                m_run[mt][r] = m_new;
                float ls = 0.0f;
#pragma unroll
                for (int j = 0; j < 8; j++) {
                    float p0 = __expf(s[mt][j][2 * r] - m_new);
                    float p1 = __expf(s[mt][j][2 * r + 1] - m_new);
                    s[mt][j][2 * r] = p0; s[mt][j][2 * r + 1] = p1;
                    ls += p0 + p1;
                }
                ls += __shfl_xor_sync(0xffffffffu, ls, 1);
                ls += __shfl_xor_sync(0xffffffffu, ls, 2);
                l_run[mt][r] = l_run[mt][r] * alpha + ls;
#pragma unroll
                for (int j = 0; j < 8; j++) {
                    o[mt][j][2 * r] *= alpha;
                    o[mt][j][2 * r + 1] *= alpha;
                }
            }

#pragma unroll
        for (int mt = 0; mt < 2; mt++)
#pragma unroll
            for (int j = 0; j < 8; j++) {
                const int col = j * 8 + t * 2;
                const int r0 = (qb + mt * 16 + g) * PP + col;
                uint2 v0 = make_uint2(f2tf(s[mt][j][0]), f2tf(s[mt][j][1]));
                uint2 v1 = make_uint2(f2tf(s[mt][j][2]), f2tf(s[mt][j][3]));
                *(uint2*)&Ps[r0] = v0;
                *(uint2*)&Ps[r0 + 8 * PP] = v1;
            }
        __syncwarp();

#pragma unroll
        for (int kv = 0; kv < 8; kv++) {
            unsigned vb[8][2];
#pragma unroll
            for (int j = 0; j < 8; j++) {
                vb[j][0] = Vs[(kv * 8 + t) * VP + j * 8 + g];
                vb[j][1] = Vs[(kv * 8 + t + 4) * VP + j * 8 + g];
            }
#pragma unroll
            for (int mt = 0; mt < 2; mt++) {
                unsigned pa[4];
                const int r0 = (qb + mt * 16 + g) * PP + kv * 8 + t;
                pa[0] = Ps[r0];
                pa[1] = Ps[r0 + 8 * PP];
                pa[2] = Ps[r0 + 4];
                pa[3] = Ps[r0 + 8 * PP + 4];
#pragma unroll
                for (int j = 0; j < 8; j++)
                    mma8(o[mt][j][0], o[mt][j][1], o[mt][j][2], o[mt][j][3],
                         pa[0], pa[1], pa[2], pa[3], vb[j][0], vb[j][1]);
            }
        }
    }

#pragma unroll
    for (int mt = 0; mt < 2; mt++) {
        const float inv0 = 1.0f / l_run[mt][0];
        const float inv1 = 1.0f / l_run[mt][1];
#pragma unroll
        for (int j = 0; j < 8; j++) {
            const int d = h * DHX + j * 8 + t * 2;
            size_t r0 = ((size_t)b * TT + q0 + qb + mt * 16 + g) * DD + d;
            size_t r1 = r0 + (size_t)8 * DD;
            float2 v0 = make_float2(o[mt][j][0] * inv0, o[mt][j][1] * inv0);
            float2 v1 = make_float2(o[mt][j][2] * inv1, o[mt][j][3] * inv1);
            *(float2*)&g_ctx[r0] = v0;
            *(float2*)&g_ctx[r1] = v1;
        }
    }
}

// ---------------------------------------------------------------------------
// kernel_launch
// ---------------------------------------------------------------------------
extern "C" void kernel_launch(void* const* d_in, const int* in_sizes, int n_in,
                              void* d_out, int out_size)
{
    const float* query = (const float*)d_in[0];
    const float* key_  = (const float*)d_in[1];
    const float* value = (const float*)d_in[2];
    const float* sp    = (const float*)d_in[3];
    const float* edg   = (const float*)d_in[4];
    const unsigned int* mask = (const unsigned int*)d_in[5];
    const float* Wq = (const float*)d_in[6];
    const float* bq = (const float*)d_in[7];
    const float* Wk = (const float*)d_in[8];
    const float* bk = (const float*)d_in[9];
    const float* Wv = (const float*)d_in[10];
    const float* bv = (const float*)d_in[11];
    const float* Wo = (const float*)d_in[12];
    const float* bo = (const float*)d_in[13];
    float* out = (float*)d_out;

    float* gq;   cudaGetSymbolAddress((void**)&gq, g_q);
    float* gk;   cudaGetSymbolAddress((void**)&gk, g_k);
    float* gv;   cudaGetSymbolAddress((void**)&gv, g_v);
    float* gctx; cudaGetSymbolAddress((void**)&gctx, g_ctx);
    float* gb;   cudaGetSymbolAddress((void**)&gb, g_bias);

    bias_fuse<<<BB * TT * TT / 4 / 256, 256>>>((const float4*)sp, (const float4*)edg,
                                               mask, (float4*)gb);

    cudaFuncSetAttribute(gemm_cp<0>, cudaFuncAttributeMaxDynamicSharedMemorySize, GSMEM);
    cudaFuncSetAttribute(gemm_cp<1>, cudaFuncAttributeMaxDynamicSharedMemorySize, GSMEM);

    // fused QKV projections
    dim3 grid_qkv(DD / 128, MROWS / 128, 3);   // (8, 64, 3)
    gemm_cp<0><<<grid_qkv, 256, GSMEM>>>(query, key_, value, Wq, Wk, Wv,
                                         bq, bk, bv, gq, gk, gv);

    cudaFuncSetAttribute(attn_tc2, cudaFuncAttributeMaxDynamicSharedMemorySize, ATTN_SMEM);
    dim3 attn_grid(TT / 128, HH, BB);  // (8, 16, 8)
    attn_tc2<<<attn_grid, 128, ATTN_SMEM>>>(gb);

    dim3 grid_o(DD / 128, MROWS / 128, 1);
    gemm_cp<1><<<grid_o, 256, GSMEM>>>(gctx, gctx, gctx, Wo, Wo, Wo,
                                       bo, bo, bo, out, out, out);
}

// round 8
// speedup vs baseline: 6.3212x; 1.6347x over previous
#include <cuda_runtime.h>
#include <cuda_fp16.h>
#include <cstdint>

#define BB 8
#define TT 1024
#define DD 1024
#define HH 16
#define DHX 64
#define MROWS (BB*TT)   // 8192

// Scratch
__device__ __half g_qh[MROWS * DD];   // (B,H,T,DH) fp16
__device__ __half g_kh[MROWS * DD];   // (B,H,T,DH) fp16
__device__ __half g_vh[MROWS * DD];   // (B,H,T,DH) fp16
__device__ float  g_ctx[MROWS * DD];  // (B,T,D) f32
__device__ float  g_bias[BB * TT * TT];

// ---------------------------------------------------------------------------
// helpers
// ---------------------------------------------------------------------------
__device__ __forceinline__ unsigned packh2(float lo, float hi) {
    __half2 h = __floats2half2_rn(lo, hi);   // .x = lo (low half), .y = hi
    return *reinterpret_cast<unsigned*>(&h);
}
__device__ __forceinline__ uint32_t smem_u32(const void* p) {
    uint32_t a;
    asm("{ .reg .u64 t; cvta.to.shared.u64 t, %1; cvt.u32.u64 %0, t; }" : "=r"(a) : "l"(p));
    return a;
}
__device__ __forceinline__ void ldsm4(unsigned& r0, unsigned& r1, unsigned& r2, unsigned& r3,
                                      uint32_t addr) {
    asm volatile("ldmatrix.sync.aligned.m8n8.x4.shared.b16 {%0,%1,%2,%3}, [%4];"
                 : "=r"(r0), "=r"(r1), "=r"(r2), "=r"(r3) : "r"(addr));
}
__device__ __forceinline__ void ldsm4t(unsigned& r0, unsigned& r1, unsigned& r2, unsigned& r3,
                                       uint32_t addr) {
    asm volatile("ldmatrix.sync.aligned.m8n8.x4.trans.shared.b16 {%0,%1,%2,%3}, [%4];"
                 : "=r"(r0), "=r"(r1), "=r"(r2), "=r"(r3) : "r"(addr));
}
__device__ __forceinline__ void mma16(float& c0, float& c1, float& c2, float& c3,
                                      unsigned a0, unsigned a1, unsigned a2, unsigned a3,
                                      unsigned b0, unsigned b1) {
    asm("mma.sync.aligned.m16n8k16.row.col.f32.f16.f16.f32 "
        "{%0,%1,%2,%3}, {%4,%5,%6,%7}, {%8,%9}, {%0,%1,%2,%3};"
        : "+f"(c0), "+f"(c1), "+f"(c2), "+f"(c3)
        : "r"(a0), "r"(a1), "r"(a2), "r"(a3), "r"(b0), "r"(b1));
}

// ---------------------------------------------------------------------------
// bias pre-fusion: g_bias = mask ? -1e30 : sp + ed
// ---------------------------------------------------------------------------
__global__ __launch_bounds__(256)
void bias_fuse(const float4* __restrict__ sp4, const float4* __restrict__ ed4,
               const unsigned* __restrict__ mask, float4* __restrict__ out4)
{
    const int idx = blockIdx.x * 256 + threadIdx.x;
    const int b = idx >> 18;
    const int e4 = idx & 262143;
    const int col = (e4 & 255) << 2;
    const uint4 mk = *(const uint4*)&mask[b * TT + col];
    const float4 s = sp4[idx];
    const float4 e = ed4[idx];
    float4 o;
    o.x = mk.x ? -1e30f : (s.x + e.x);
    o.y = mk.y ? -1e30f : (s.y + e.y);
    o.z = mk.z ? -1e30f : (s.z + e.z);
    o.w = mk.w ? -1e30f : (s.w + e.w);
    out4[idx] = o;
}

// ---------------------------------------------------------------------------
// fp16 tensor-core GEMM: C[8192,1024] = A @ W + bias  (f32 in, fp16 mma, f32 acc)
// BM=128 BN=128 BK=32, double-buffered smem (fp16), 256 thr = 8 warps (4m x 2n),
// warp tile 32x64 via m16n8k16. Fragments via ldmatrix (A: x4, B: x4.trans).
// smem pitches (fp16x2 words): A 20 (bank 20r%32 distinct), B 68 (4r distinct).
// MODE 0: QKV fused via blockIdx.z, fp16 scatter to (B,H,T,DH).
// MODE 1: f32 row-major out.
// ---------------------------------------------------------------------------
#define AP2 20
#define BP2 68

template<int MODE>
__global__ __launch_bounds__(256, 2)
void gemm_h(const float* __restrict__ A0, const float* __restrict__ A1, const float* __restrict__ A2,
            const float* __restrict__ W0, const float* __restrict__ W1, const float* __restrict__ W2,
            const float* __restrict__ bp0, const float* __restrict__ bp1, const float* __restrict__ bp2,
            void* __restrict__ O0, void* __restrict__ O1, void* __restrict__ O2)
{
    __shared__ unsigned A2s[2][128 * AP2];
    __shared__ unsigned B2s[2][32 * BP2];

    const int tid  = threadIdx.x;
    const int lane = tid & 31;
    const int warp = tid >> 5;
    const int g = lane >> 2;
    const int t = lane & 3;
    const int wm = warp >> 1;   // 0..3
    const int wn = warp & 1;    // 0..1
    const int m0 = blockIdx.y * 128;
    const int n0 = blockIdx.x * 128;

    const float* A = A0; const float* W = W0; const float* bias = bp0; void* out = O0;
    if (MODE == 0) {
        if (blockIdx.z == 1) { A = A1; W = W1; bias = bp1; out = O1; }
        else if (blockIdx.z == 2) { A = A2; W = W2; bias = bp2; out = O2; }
    }

    // ldmatrix lane constants
    const int a_row = (lane & 7) + ((lane >> 3) & 1) * 8;   // A (non-trans)
    const int a_kw  = (lane >> 4) * 4;
    const int b_krow = (lane & 7) + ((lane >> 3) & 1) * 8;  // B (trans)
    const int b_j4   = (lane >> 4) * 4;

    const uint32_t sA[2] = { smem_u32(A2s[0]), smem_u32(A2s[1]) };
    const uint32_t sB[2] = { smem_u32(B2s[0]), smem_u32(B2s[1]) };

    float4 ra[4], rw[4];
    auto ldg = [&](int kt) {
        const int k0 = kt * 32;
#pragma unroll
        for (int it = 0; it < 4; it++) {
            int idx = tid + it * 256;
            int m = idx >> 3, ch = idx & 7;
            ra[it] = *(const float4*)&A[(size_t)(m0 + m) * DD + k0 + ch * 4];
            int kk = idx >> 5, nn = (idx & 31) << 2;
            rw[it] = *(const float4*)&W[(size_t)(k0 + kk) * DD + n0 + nn];
        }
    };
    auto sts = [&](int buf) {
#pragma unroll
        for (int it = 0; it < 4; it++) {
            int idx = tid + it * 256;
            int m = idx >> 3, ch = idx & 7;
            uint2 av = make_uint2(packh2(ra[it].x, ra[it].y), packh2(ra[it].z, ra[it].w));
            *(uint2*)&A2s[buf][m * AP2 + ch * 2] = av;
            int kk = idx >> 5, u = idx & 31;
            uint2 wv = make_uint2(packh2(rw[it].x, rw[it].y), packh2(rw[it].z, rw[it].w));
            *(uint2*)&B2s[buf][kk * BP2 + u * 2] = wv;
        }
    };

    ldg(0); sts(0);
    __syncthreads();

    float acc[2][8][4];
#pragma unroll
    for (int i = 0; i < 2; i++)
#pragma unroll
        for (int j = 0; j < 8; j++)
#pragma unroll
            for (int c = 0; c < 4; c++) acc[i][j][c] = 0.0f;

    for (int kt = 0; kt < 32; kt++) {
        const int cur = kt & 1;
        if (kt + 1 < 32) ldg(kt + 1);

#pragma unroll
        for (int ks = 0; ks < 2; ks++) {
            unsigned af[2][4];
#pragma unroll
            for (int i = 0; i < 2; i++)
                ldsm4(af[i][0], af[i][1], af[i][2], af[i][3],
                      sA[cur] + (uint32_t)(((wm * 32 + i * 16 + a_row) * AP2) + ks * 8 + a_kw) * 4);
            unsigned bf[8][2];
#pragma unroll
            for (int jp = 0; jp < 4; jp++)
                ldsm4t(bf[2 * jp][0], bf[2 * jp][1], bf[2 * jp + 1][0], bf[2 * jp + 1][1],
                       sB[cur] + (uint32_t)(((ks * 16 + b_krow) * BP2) + wn * 32 + jp * 8 + b_j4) * 4);
#pragma unroll
            for (int i = 0; i < 2; i++)
#pragma unroll
                for (int j = 0; j < 8; j++)
                    mma16(acc[i][j][0], acc[i][j][1], acc[i][j][2], acc[i][j][3],
                          af[i][0], af[i][1], af[i][2], af[i][3],
                          bf[j][0], bf[j][1]);
        }

        if (kt + 1 < 32) sts((kt + 1) & 1);
        __syncthreads();
    }

    // epilogue (acc layout: c0,c1 = row g cols 2t,2t+1; c2,c3 = row g+8)
#pragma unroll
    for (int i = 0; i < 2; i++) {
#pragma unroll
        for (int j = 0; j < 8; j++) {
            const int n = n0 + wn * 64 + j * 8 + t * 2;
            const float2 bb = *(const float2*)&bias[n];
#pragma unroll
            for (int h2 = 0; h2 < 2; h2++) {
                const int m = m0 + wm * 32 + i * 16 + g + h2 * 8;
                float vx = acc[i][j][h2 * 2 + 0] + bb.x;
                float vy = acc[i][j][h2 * 2 + 1] + bb.y;
                if (MODE == 0) {
                    int bidx = m >> 10, tt = m & 1023;
                    int hh = n >> 6, d = n & 63;
                    __half2 hv = __floats2half2_rn(vx, vy);
                    *(__half2*)&((__half*)out)[(((size_t)(bidx * HH + hh) << 10) + tt) * DHX + d] = hv;
                } else {
                    *(float2*)&((float*)out)[(size_t)m * DD + n] = make_float2(vx, vy);
                }
            }
        }
    }
}

// ---------------------------------------------------------------------------
// Fused flash attention v3 (fp16 mma.sync m16n8k16).
// Block = (b, h, 128 q-rows), 128 thr = 4 warps, warp = 32 q-rows (2 m16 tiles).
// Q/K/V fp16 from GEMM. Fragments via ldmatrix (Q,K: x4; V: x4.trans).
// P never touches smem: S accumulators repack directly into A fragments.
// smem pitch 36 words (4r distinct banks).
// ---------------------------------------------------------------------------
#define QP2 36

__global__ __launch_bounds__(128)
void attn_h(const float* __restrict__ gb)
{
    __shared__ unsigned Q2[128 * QP2];
    __shared__ unsigned K2[64 * QP2];
    __shared__ unsigned V2[64 * QP2];

    const int tid  = threadIdx.x;
    const int lane = tid & 31;
    const int warp = tid >> 5;
    const int g = lane >> 2;
    const int t = lane & 3;
    const int q0 = blockIdx.x * 128;
    const int h  = blockIdx.y;
    const int b  = blockIdx.z;
    const int qb = warp * 32;

    const __half* Qg = g_qh + (size_t)(b * HH + h) * TT * DHX;
    const __half* Kg = g_kh + (size_t)(b * HH + h) * TT * DHX;
    const __half* Vg = g_vh + (size_t)(b * HH + h) * TT * DHX;

    const uint32_t sQ = smem_u32(Q2);
    const uint32_t sK = smem_u32(K2);
    const uint32_t sV = smem_u32(V2);

    // lane constants
    const int a_row = (lane & 7) + ((lane >> 3) & 1) * 8;       // Q (A, non-trans)
    const int a_kw  = (lane >> 4) * 4;
    const int k_row = (lane & 7) + ((lane >> 4) & 1) * 8;       // K (B, non-trans, 2 n-tiles)
    const int k_kw  = ((lane >> 3) & 1) * 4;
    const int v_krow = (lane & 7) + ((lane >> 3) & 1) * 8;      // V (B, trans)
    const int v_jw   = (lane >> 4) * 4;

    // load Q tile (128 x 64 fp16) -- pure copy
#pragma unroll
    for (int it = 0; it < 8; it++) {
        int idx = tid + it * 128;
        int r = idx >> 3, u = idx & 7;
        uint4 qv = *(const uint4*)&Qg[(size_t)(q0 + r) * DHX + u * 8];
        *(uint4*)&Q2[r * QP2 + u * 4] = qv;
    }
    __syncthreads();

    // Q fragments register-resident: 2 m-tiles x 4 k16-steps
    unsigned qf[2][4][4];
#pragma unroll
    for (int mt = 0; mt < 2; mt++)
#pragma unroll
        for (int ks = 0; ks < 4; ks++)
            ldsm4(qf[mt][ks][0], qf[mt][ks][1], qf[mt][ks][2], qf[mt][ks][3],
                  sQ + (uint32_t)(((qb + mt * 16 + a_row) * QP2) + ks * 8 + a_kw) * 4);

    float o[2][8][4];
#pragma unroll
    for (int mt = 0; mt < 2; mt++)
#pragma unroll
        for (int j = 0; j < 8; j++)
#pragma unroll
            for (int c = 0; c < 4; c++) o[mt][j][c] = 0.0f;
    float m_run[2][2] = {{-3e38f, -3e38f}, {-3e38f, -3e38f}};
    float l_run[2][2] = {{0.0f, 0.0f}, {0.0f, 0.0f}};

    for (int kt = 0; kt < 16; kt++) {
        const int k0 = kt * 64;
        __syncthreads();

        // load K,V tiles (64 x 64 fp16 each)
#pragma unroll
        for (int it = 0; it < 4; it++) {
            int idx = tid + it * 128;
            int r = idx >> 3, u = idx & 7;
            uint4 kv = *(const uint4*)&Kg[(size_t)(k0 + r) * DHX + u * 8];
            *(uint4*)&K2[r * QP2 + u * 4] = kv;
            uint4 vv = *(const uint4*)&Vg[(size_t)(k0 + r) * DHX + u * 8];
            *(uint4*)&V2[r * QP2 + u * 4] = vv;
        }
        __syncthreads();

        // S = Q K^T : k-dim = 64 (4 k16 steps), n = 64 tokens (8 tiles)
        float s[2][8][4];
#pragma unroll
        for (int mt = 0; mt < 2; mt++)
#pragma unroll
            for (int j = 0; j < 8; j++)
#pragma unroll
                for (int c = 0; c < 4; c++) s[mt][j][c] = 0.0f;

#pragma unroll
        for (int ks = 0; ks < 4; ks++) {
            unsigned kb[8][2];
#pragma unroll
            for (int jp = 0; jp < 4; jp++)
                ldsm4(kb[2 * jp][0], kb[2 * jp][1], kb[2 * jp + 1][0], kb[2 * jp + 1][1],
                      sK + (uint32_t)(((jp * 16 + k_row) * QP2) + ks * 8 + k_kw) * 4);
#pragma unroll
            for (int mt = 0; mt < 2; mt++)
#pragma unroll
                for (int j = 0; j < 8; j++)
                    mma16(s[mt][j][0], s[mt][j][1], s[mt][j][2], s[mt][j][3],
                          qf[mt][ks][0], qf[mt][ks][1], qf[mt][ks][2], qf[mt][ks][3],
                          kb[j][0], kb[j][1]);
        }

        // scale + fused bias
#pragma unroll
        for (int mt = 0; mt < 2; mt++)
#pragma unroll
            for (int j = 0; j < 8; j++) {
                const int col = k0 + j * 8 + t * 2;
                const size_t i0 = ((size_t)b * TT + (q0 + qb + mt * 16 + g)) * TT + col;
                float2 b0 = *(const float2*)&gb[i0];
                float2 b1 = *(const float2*)&gb[i0 + (size_t)8 * TT];
                s[mt][j][0] = s[mt][j][0] * 0.125f + b0.x;
                s[mt][j][1] = s[mt][j][1] * 0.125f + b0.y;
                s[mt][j][2] = s[mt][j][2] * 0.125f + b1.x;
                s[mt][j][3] = s[mt][j][3] * 0.125f + b1.y;
            }

        // online softmax
#pragma unroll
        for (int mt = 0; mt < 2; mt++)
#pragma unroll
            for (int r = 0; r < 2; r++) {
                float mx = -3e38f;
#pragma unroll
                for (int j = 0; j < 8; j++)
                    mx = fmaxf(mx, fmaxf(s[mt][j][2 * r], s[mt][j][2 * r + 1]));
                mx = fmaxf(mx, __shfl_xor_sync(0xffffffffu, mx, 1));
                mx = fmaxf(mx, __shfl_xor_sync(0xffffffffu, mx, 2));
                float m_new = fmaxf(m_run[mt][r], mx);
                float alpha = __expf(m_run[mt][r] - m_new);
                m_run[mt][r] = m_new;
                float ls = 0.0f;
#pragma unroll
                for (int j = 0; j < 8; j++) {
                    float p0 = __expf(s[mt][j][2 * r] - m_new);
                    float p1 = __expf(s[mt][j][2 * r + 1] - m_new);
                    s[mt][j][2 * r] = p0; s[mt][j][2 * r + 1] = p1;
                    ls += p0 + p1;
                }
                ls += __shfl_xor_sync(0xffffffffu, ls, 1);
                ls += __shfl_xor_sync(0xffffffffu, ls, 2);
                l_run[mt][r] = l_run[mt][r] * alpha + ls;
#pragma unroll
                for (int j = 0; j < 8; j++) {
                    o[mt][j][2 * r] *= alpha;
                    o[mt][j][2 * r + 1] *= alpha;
                }
            }

        // pack P into A fragments IN REGISTERS (no smem round-trip).
        // k-chunk c (16 tokens = S tiles 2c, 2c+1):
        //   a0 = P[g][16c+2t,+1]   = pack(s[2c][0], s[2c][1])
        //   a1 = P[g+8][...]       = pack(s[2c][2], s[2c][3])
        //   a2 = P[g][16c+8+2t,+1] = pack(s[2c+1][0], s[2c+1][1])
        //   a3 = P[g+8][...]       = pack(s[2c+1][2], s[2c+1][3])
        unsigned pf[2][4][4];
#pragma unroll
        for (int mt = 0; mt < 2; mt++)
#pragma unroll
            for (int c = 0; c < 4; c++) {
                pf[mt][c][0] = packh2(s[mt][2 * c][0], s[mt][2 * c][1]);
                pf[mt][c][1] = packh2(s[mt][2 * c][2], s[mt][2 * c][3]);
                pf[mt][c][2] = packh2(s[mt][2 * c + 1][0], s[mt][2 * c + 1][1]);
                pf[mt][c][3] = packh2(s[mt][2 * c + 1][2], s[mt][2 * c + 1][3]);
            }

        // O += P @ V : k = 64 tokens (4 k16 steps), n = 64 dh (8 tiles)
#pragma unroll
        for (int kv = 0; kv < 4; kv++) {
            unsigned vb[8][2];
#pragma unroll
            for (int jp = 0; jp < 4; jp++)
                ldsm4t(vb[2 * jp][0], vb[2 * jp][1], vb[2 * jp + 1][0], vb[2 * jp + 1][1],
                       sV + (uint32_t)(((kv * 16 + v_krow) * QP2) + jp * 8 + v_jw) * 4);
#pragma unroll
            for (int mt = 0; mt < 2; mt++)
#pragma unroll
                for (int j = 0; j < 8; j++)
                    mma16(o[mt][j][0], o[mt][j][1], o[mt][j][2], o[mt][j][3],
                          pf[mt][kv][0], pf[mt][kv][1], pf[mt][kv][2], pf[mt][kv][3],
                          vb[j][0], vb[j][1]);
        }
    }

    // normalize + write (B,T,D) f32
#pragma unroll
    for (int mt = 0; mt < 2; mt++) {
        const float inv0 = 1.0f / l_run[mt][0];
        const float inv1 = 1.0f / l_run[mt][1];
#pragma unroll
        for (int j = 0; j < 8; j++) {
            const int d = h * DHX + j * 8 + t * 2;
            size_t r0 = ((size_t)b * TT + q0 + qb + mt * 16 + g) * DD + d;
            size_t r1 = r0 + (size_t)8 * DD;
            *(float2*)&g_ctx[r0] = make_float2(o[mt][j][0] * inv0, o[mt][j][1] * inv0);
            *(float2*)&g_ctx[r1] = make_float2(o[mt][j][2] * inv1, o[mt][j][3] * inv1);
        }
    }
}

// ---------------------------------------------------------------------------
// kernel_launch
// ---------------------------------------------------------------------------
extern "C" void kernel_launch(void* const* d_in, const int* in_sizes, int n_in,
                              void* d_out, int out_size)
{
    const float* query = (const float*)d_in[0];
    const float* key_  = (const float*)d_in[1];
    const float* value = (const float*)d_in[2];
    const float* sp    = (const float*)d_in[3];
    const float* edg   = (const float*)d_in[4];
    const unsigned int* mask = (const unsigned int*)d_in[5];
    const float* Wq = (const float*)d_in[6];
    const float* bq = (const float*)d_in[7];
    const float* Wk = (const float*)d_in[8];
    const float* bk = (const float*)d_in[9];
    const float* Wv = (const float*)d_in[10];
    const float* bv = (const float*)d_in[11];
    const float* Wo = (const float*)d_in[12];
    const float* bo = (const float*)d_in[13];
    float* out = (float*)d_out;

    __half* gq;  cudaGetSymbolAddress((void**)&gq, g_qh);
    __half* gk;  cudaGetSymbolAddress((void**)&gk, g_kh);
    __half* gv;  cudaGetSymbolAddress((void**)&gv, g_vh);
    float* gctx; cudaGetSymbolAddress((void**)&gctx, g_ctx);
    float* gb;   cudaGetSymbolAddress((void**)&gb, g_bias);

    bias_fuse<<<BB * TT * TT / 4 / 256, 256>>>((const float4*)sp, (const float4*)edg,
                                               mask, (float4*)gb);

    // fused QKV projections (fp16 out)
    dim3 grid_qkv(DD / 128, MROWS / 128, 3);
    gemm_h<0><<<grid_qkv, 256>>>(query, key_, value, Wq, Wk, Wv,
                                 bq, bk, bv, gq, gk, gv);

    dim3 attn_grid(TT / 128, HH, BB);   // (8, 16, 8)
    attn_h<<<attn_grid, 128>>>(gb);

    // output projection (f32 out)
    dim3 grid_o(DD / 128, MROWS / 128, 1);
    gemm_h<1><<<grid_o, 256>>>(gctx, gctx, gctx, Wo, Wo, Wo,
                               bo, bo, bo, out, out, out);
}

// round 9
// speedup vs baseline: 7.1176x; 1.1260x over previous
#include <cuda_runtime.h>
#include <cuda_fp16.h>
#include <cstdint>

#define BB 8
#define TT 1024
#define DD 1024
#define HH 16
#define DHX 64
#define MROWS (BB*TT)   // 8192

// fp16 scratch
__device__ __half g_xq[MROWS * DD];   // inputs converted
__device__ __half g_xk[MROWS * DD];
__device__ __half g_xv[MROWS * DD];
__device__ __half g_wq[DD * DD];
__device__ __half g_wk[DD * DD];
__device__ __half g_wv[DD * DD];
__device__ __half g_wo[DD * DD];
__device__ __half g_qh[MROWS * DD];   // projections (B,H,T,DH)
__device__ __half g_kh[MROWS * DD];
__device__ __half g_vh[MROWS * DD];
__device__ __half g_ctxh[MROWS * DD]; // attention output (B,T,D)
__device__ float  g_bias[BB * TT * TT];

// ---------------------------------------------------------------------------
// helpers
// ---------------------------------------------------------------------------
__device__ __forceinline__ unsigned packh2(float lo, float hi) {
    __half2 h = __floats2half2_rn(lo, hi);
    return *reinterpret_cast<unsigned*>(&h);
}
__device__ __forceinline__ uint32_t smem_u32(const void* p) {
    uint32_t a;
    asm("{ .reg .u64 t; cvta.to.shared.u64 t, %1; cvt.u32.u64 %0, t; }" : "=r"(a) : "l"(p));
    return a;
}
__device__ __forceinline__ void ldsm4(unsigned& r0, unsigned& r1, unsigned& r2, unsigned& r3,
                                      uint32_t addr) {
    asm volatile("ldmatrix.sync.aligned.m8n8.x4.shared.b16 {%0,%1,%2,%3}, [%4];"
                 : "=r"(r0), "=r"(r1), "=r"(r2), "=r"(r3) : "r"(addr));
}
__device__ __forceinline__ void ldsm4t(unsigned& r0, unsigned& r1, unsigned& r2, unsigned& r3,
                                       uint32_t addr) {
    asm volatile("ldmatrix.sync.aligned.m8n8.x4.trans.shared.b16 {%0,%1,%2,%3}, [%4];"
                 : "=r"(r0), "=r"(r1), "=r"(r2), "=r"(r3) : "r"(addr));
}
__device__ __forceinline__ void mma16(float& c0, float& c1, float& c2, float& c3,
                                      unsigned a0, unsigned a1, unsigned a2, unsigned a3,
                                      unsigned b0, unsigned b1) {
    asm("mma.sync.aligned.m16n8k16.row.col.f32.f16.f16.f32 "
        "{%0,%1,%2,%3}, {%4,%5,%6,%7}, {%8,%9}, {%0,%1,%2,%3};"
        : "+f"(c0), "+f"(c1), "+f"(c2), "+f"(c3)
        : "r"(a0), "r"(a1), "r"(a2), "r"(a3), "r"(b0), "r"(b1));
}
#define CP16(dst, src) \
    asm volatile("cp.async.cg.shared.global [%0], [%1], 16;" :: "r"(dst), "l"(src))
#define CP_COMMIT() asm volatile("cp.async.commit_group;" ::: "memory")
#define CP_WAIT1()  asm volatile("cp.async.wait_group 1;" ::: "memory")

// ---------------------------------------------------------------------------
// f32 -> fp16 conversion (elementwise, float4 -> 4 halves)
// ---------------------------------------------------------------------------
__global__ __launch_bounds__(256)
void to_half(const float4* __restrict__ src, uint2* __restrict__ dst)
{
    const int i = blockIdx.x * 256 + threadIdx.x;
    float4 v = src[i];
    dst[i] = make_uint2(packh2(v.x, v.y), packh2(v.z, v.w));
}

// ---------------------------------------------------------------------------
// bias pre-fusion: g_bias = mask ? -1e30 : sp + ed  (f32)
// ---------------------------------------------------------------------------
__global__ __launch_bounds__(256)
void bias_fuse(const float4* __restrict__ sp4, const float4* __restrict__ ed4,
               const unsigned* __restrict__ mask, float4* __restrict__ out4)
{
    const int idx = blockIdx.x * 256 + threadIdx.x;
    const int b = idx >> 18;
    const int e4 = idx & 262143;
    const int col = (e4 & 255) << 2;
    const uint4 mk = *(const uint4*)&mask[b * TT + col];
    const float4 s = sp4[idx];
    const float4 e = ed4[idx];
    float4 o;
    o.x = mk.x ? -1e30f : (s.x + e.x);
    o.y = mk.y ? -1e30f : (s.y + e.y);
    o.z = mk.z ? -1e30f : (s.z + e.z);
    o.w = mk.w ? -1e30f : (s.w + e.w);
    out4[idx] = o;
}

// ---------------------------------------------------------------------------
// fp16 cp.async GEMM: C[8192,1024] = A @ W + bias (fp16 in, fp16 mma, f32 acc)
// BM=128 BN=128 BK=32, 3-stage cp.async, 256 thr = 8 warps (4m x 2n).
// smem word pitches: A 20, B 68 (both 16B-multiple rows; ldmatrix conflict-free,
// layouts identical to R8). MODE 0: QKV fused, fp16 scatter; MODE 1: f32 out.
// ---------------------------------------------------------------------------
#define AP2 20
#define BP2 68
#define ASTG (128 * AP2)   // 2560 words / stage
#define BSTG (32 * BP2)    // 2176 words / stage
#define GSM  (3 * (ASTG + BSTG) * 4)   // 56832 bytes

template<int MODE>
__global__ __launch_bounds__(256, 2)
void gemm_ha(const __half* __restrict__ A0, const __half* __restrict__ A1, const __half* __restrict__ A2,
             const __half* __restrict__ W0, const __half* __restrict__ W1, const __half* __restrict__ W2,
             const float* __restrict__ bp0, const float* __restrict__ bp1, const float* __restrict__ bp2,
             void* __restrict__ O0, void* __restrict__ O1, void* __restrict__ O2)
{
    extern __shared__ __align__(16) unsigned smw[];
    const uint32_t base = smem_u32(smw);

    const int tid  = threadIdx.x;
    const int lane = tid & 31;
    const int warp = tid >> 5;
    const int g = lane >> 2;
    const int t = lane & 3;
    const int wm = warp >> 1;
    const int wn = warp & 1;
    const int m0 = blockIdx.y * 128;
    const int n0 = blockIdx.x * 128;

    const __half* A = A0; const __half* W = W0; const float* bias = bp0; void* out = O0;
    if (MODE == 0) {
        if (blockIdx.z == 1) { A = A1; W = W1; bias = bp1; out = O1; }
        else if (blockIdx.z == 2) { A = A2; W = W2; bias = bp2; out = O2; }
    }

    const int a_row = (lane & 7) + ((lane >> 3) & 1) * 8;
    const int a_kw  = (lane >> 4) * 4;
    const int b_krow = (lane & 7) + ((lane >> 3) & 1) * 8;
    const int b_j4   = (lane >> 4) * 4;

    auto aw = [&](int s) { return base + (uint32_t)(s * ASTG) * 4; };
    auto bw = [&](int s) { return base + (uint32_t)(3 * ASTG + s * BSTG) * 4; };

    auto issue_stage = [&](int kt, int s) {
        const int k0 = kt * 32;
        const uint32_t ab = aw(s), bb = bw(s);
        // A: 128 rows x 4 chunks (16B = 8 halves)
#pragma unroll
        for (int it = 0; it < 2; it++) {
            int idx = tid + it * 256;
            int m = idx >> 2, ch = idx & 3;
            CP16(ab + (uint32_t)(m * AP2 + ch * 4) * 4,
                 &A[(size_t)(m0 + m) * DD + k0 + ch * 8]);
        }
        // B: 32 k-rows x 16 chunks
#pragma unroll
        for (int it = 0; it < 2; it++) {
            int idx = tid + it * 256;
            int kk = idx >> 4, c = idx & 15;
            CP16(bb + (uint32_t)(kk * BP2 + c * 4) * 4,
                 &W[(size_t)(k0 + kk) * DD + n0 + c * 8]);
        }
    };

    issue_stage(0, 0); CP_COMMIT();
    issue_stage(1, 1); CP_COMMIT();

    float acc[2][8][4];
#pragma unroll
    for (int i = 0; i < 2; i++)
#pragma unroll
        for (int j = 0; j < 8; j++)
#pragma unroll
            for (int c = 0; c < 4; c++) acc[i][j][c] = 0.0f;

    for (int kt = 0; kt < 32; kt++) {
        CP_WAIT1();
        __syncthreads();                  // stage kt visible; slot (kt+2)%3 free
        if (kt + 2 < 32) issue_stage(kt + 2, (kt + 2) % 3);
        CP_COMMIT();

        const int s = kt % 3;
        const uint32_t as = aw(s), bs = bw(s);

#pragma unroll
        for (int ks = 0; ks < 2; ks++) {
            unsigned af[2][4];
#pragma unroll
            for (int i = 0; i < 2; i++)
                ldsm4(af[i][0], af[i][1], af[i][2], af[i][3],
                      as + (uint32_t)(((wm * 32 + i * 16 + a_row) * AP2) + ks * 8 + a_kw) * 4);
            unsigned bf[8][2];
#pragma unroll
            for (int jp = 0; jp < 4; jp++)
                ldsm4t(bf[2 * jp][0], bf[2 * jp][1], bf[2 * jp + 1][0], bf[2 * jp + 1][1],
                       bs + (uint32_t)(((ks * 16 + b_krow) * BP2) + wn * 32 + jp * 8 + b_j4) * 4);
#pragma unroll
            for (int i = 0; i < 2; i++)
#pragma unroll
                for (int j = 0; j < 8; j++)
                    mma16(acc[i][j][0], acc[i][j][1], acc[i][j][2], acc[i][j][3],
                          af[i][0], af[i][1], af[i][2], af[i][3],
                          bf[j][0], bf[j][1]);
        }
    }

    // epilogue
#pragma unroll
    for (int i = 0; i < 2; i++) {
#pragma unroll
        for (int j = 0; j < 8; j++) {
            const int n = n0 + wn * 64 + j * 8 + t * 2;
            const float2 bb = *(const float2*)&bias[n];
#pragma unroll
            for (int h2 = 0; h2 < 2; h2++) {
                const int m = m0 + wm * 32 + i * 16 + g + h2 * 8;
                float vx = acc[i][j][h2 * 2 + 0] + bb.x;
                float vy = acc[i][j][h2 * 2 + 1] + bb.y;
                if (MODE == 0) {
                    int bidx = m >> 10, tt = m & 1023;
                    int hh = n >> 6, d = n & 63;
                    __half2 hv = __floats2half2_rn(vx, vy);
                    *(__half2*)&((__half*)out)[(((size_t)(bidx * HH + hh) << 10) + tt) * DHX + d] = hv;
                } else {
                    *(float2*)&((float*)out)[(size_t)m * DD + n] = make_float2(vx, vy);
                }
            }
        }
    }
}

// ---------------------------------------------------------------------------
// Fused flash attention v4: fp16 mma + 3-stage cp.async K/V pipeline.
// Block = (b, h, 128 q-rows), 128 thr = 4 warps, warp = 32 q-rows.
// Compute/fragment logic identical to R8; output packed fp16 to g_ctxh.
// smem (words): Q 128*36, then 3 stages of [K 64*36 | V 64*36].
// ---------------------------------------------------------------------------
#define QP2 36
#define QW  (128 * QP2)
#define KVW (64 * QP2)
#define ASMEM ((QW + 3 * 2 * KVW) * 4)   // 73728 bytes

__global__ __launch_bounds__(128)
void attn_h(const float* __restrict__ gb)
{
    extern __shared__ __align__(16) unsigned smw[];
    const uint32_t base = smem_u32(smw);
    unsigned* Q2 = smw;

    const int tid  = threadIdx.x;
    const int lane = tid & 31;
    const int warp = tid >> 5;
    const int g = lane >> 2;
    const int t = lane & 3;
    const int q0 = blockIdx.x * 128;
    const int h  = blockIdx.y;
    const int b  = blockIdx.z;
    const int qb = warp * 32;

    const __half* Qg = g_qh + (size_t)(b * HH + h) * TT * DHX;
    const __half* Kg = g_kh + (size_t)(b * HH + h) * TT * DHX;
    const __half* Vg = g_vh + (size_t)(b * HH + h) * TT * DHX;

    const uint32_t sQ = base;
    auto sK = [&](int s) { return base + (uint32_t)(QW + s * 2 * KVW) * 4; };
    auto sV = [&](int s) { return base + (uint32_t)(QW + s * 2 * KVW + KVW) * 4; };

    const int a_row = (lane & 7) + ((lane >> 3) & 1) * 8;
    const int a_kw  = (lane >> 4) * 4;
    const int k_row = (lane & 7) + ((lane >> 4) & 1) * 8;
    const int k_kw  = ((lane >> 3) & 1) * 4;
    const int v_krow = (lane & 7) + ((lane >> 3) & 1) * 8;
    const int v_jw   = (lane >> 4) * 4;

    auto issue_kv = [&](int kt, int s) {
        const int k0 = kt * 64;
        const uint32_t kb = sK(s), vb = sV(s);
#pragma unroll
        for (int it = 0; it < 4; it++) {
            int idx = tid + it * 128;
            int r = idx >> 3, c = idx & 7;
            CP16(kb + (uint32_t)(r * QP2 + c * 4) * 4, &Kg[(size_t)(k0 + r) * DHX + c * 8]);
            CP16(vb + (uint32_t)(r * QP2 + c * 4) * 4, &Vg[(size_t)(k0 + r) * DHX + c * 8]);
        }
    };

    // Q tile (plain vector loads, once)
#pragma unroll
    for (int it = 0; it < 8; it++) {
        int idx = tid + it * 128;
        int r = idx >> 3, u = idx & 7;
        uint4 qv = *(const uint4*)&Qg[(size_t)(q0 + r) * DHX + u * 8];
        *(uint4*)&Q2[r * QP2 + u * 4] = qv;
    }
    issue_kv(0, 0); CP_COMMIT();
    issue_kv(1, 1); CP_COMMIT();
    __syncthreads();

    unsigned qf[2][4][4];
#pragma unroll
    for (int mt = 0; mt < 2; mt++)
#pragma unroll
        for (int ks = 0; ks < 4; ks++)
            ldsm4(qf[mt][ks][0], qf[mt][ks][1], qf[mt][ks][2], qf[mt][ks][3],
                  sQ + (uint32_t)(((qb + mt * 16 + a_row) * QP2) + ks * 8 + a_kw) * 4);

    float o[2][8][4];
#pragma unroll
    for (int mt = 0; mt < 2; mt++)
#pragma unroll
        for (int j = 0; j < 8; j++)
#pragma unroll
            for (int c = 0; c < 4; c++) o[mt][j][c] = 0.0f;
    float m_run[2][2] = {{-3e38f, -3e38f}, {-3e38f, -3e38f}};
    float l_run[2][2] = {{0.0f, 0.0f}, {0.0f, 0.0f}};

    for (int kt = 0; kt < 16; kt++) {
        const int k0 = kt * 64;
        CP_WAIT1();
        __syncthreads();
        if (kt + 2 < 16) issue_kv(kt + 2, (kt + 2) % 3);
        CP_COMMIT();

        const int s = kt % 3;
        const uint32_t kbs = sK(s), vbs = sV(s);

        // S = Q K^T
        float sc[2][8][4];
#pragma unroll
        for (int mt = 0; mt < 2; mt++)
#pragma unroll
            for (int j = 0; j < 8; j++)
#pragma unroll
                for (int c = 0; c < 4; c++) sc[mt][j][c] = 0.0f;

#pragma unroll
        for (int ks = 0; ks < 4; ks++) {
            unsigned kb[8][2];
#pragma unroll
            for (int jp = 0; jp < 4; jp++)
                ldsm4(kb[2 * jp][0], kb[2 * jp][1], kb[2 * jp + 1][0], kb[2 * jp + 1][1],
                      kbs + (uint32_t)(((jp * 16 + k_row) * QP2) + ks * 8 + k_kw) * 4);
#pragma unroll
            for (int mt = 0; mt < 2; mt++)
#pragma unroll
                for (int j = 0; j < 8; j++)
                    mma16(sc[mt][j][0], sc[mt][j][1], sc[mt][j][2], sc[mt][j][3],
                          qf[mt][ks][0], qf[mt][ks][1], qf[mt][ks][2], qf[mt][ks][3],
                          kb[j][0], kb[j][1]);
        }

        // scale + fused bias (f32)
#pragma unroll
        for (int mt = 0; mt < 2; mt++)
#pragma unroll
            for (int j = 0; j < 8; j++) {
                const int col = k0 + j * 8 + t * 2;
                const size_t i0 = ((size_t)b * TT + (q0 + qb + mt * 16 + g)) * TT + col;
                float2 b0 = *(const float2*)&gb[i0];
                float2 b1 = *(const float2*)&gb[i0 + (size_t)8 * TT];
                sc[mt][j][0] = sc[mt][j][0] * 0.125f + b0.x;
                sc[mt][j][1] = sc[mt][j][1] * 0.125f + b0.y;
                sc[mt][j][2] = sc[mt][j][2] * 0.125f + b1.x;
                sc[mt][j][3] = sc[mt][j][3] * 0.125f + b1.y;
            }

        // online softmax
#pragma unroll
        for (int mt = 0; mt < 2; mt++)
#pragma unroll
            for (int r = 0; r < 2; r++) {
                float mx = -3e38f;
#pragma unroll
                for (int j = 0; j < 8; j++)
                    mx = fmaxf(mx, fmaxf(sc[mt][j][2 * r], sc[mt][j][2 * r + 1]));
                mx = fmaxf(mx, __shfl_xor_sync(0xffffffffu, mx, 1));
                mx = fmaxf(mx, __shfl_xor_sync(0xffffffffu, mx, 2));
                float m_new = fmaxf(m_run[mt][r], mx);
                float alpha = __expf(m_run[mt][r] - m_new);
                m_run[mt][r] = m_new;
                float ls = 0.0f;
#pragma unroll
                for (int j = 0; j < 8; j++) {
                    float p0 = __expf(sc[mt][j][2 * r] - m_new);
                    float p1 = __expf(sc[mt][j][2 * r + 1] - m_new);
                    sc[mt][j][2 * r] = p0; sc[mt][j][2 * r + 1] = p1;
                    ls += p0 + p1;
                }
                ls += __shfl_xor_sync(0xffffffffu, ls, 1);
                ls += __shfl_xor_sync(0xffffffffu, ls, 2);
                l_run[mt][r] = l_run[mt][r] * alpha + ls;
#pragma unroll
                for (int j = 0; j < 8; j++) {
                    o[mt][j][2 * r] *= alpha;
                    o[mt][j][2 * r + 1] *= alpha;
                }
            }

        // pack P into A fragments in registers
        unsigned pf[2][4][4];
#pragma unroll
        for (int mt = 0; mt < 2; mt++)
#pragma unroll
            for (int c = 0; c < 4; c++) {
                pf[mt][c][0] = packh2(sc[mt][2 * c][0], sc[mt][2 * c][1]);
                pf[mt][c][1] = packh2(sc[mt][2 * c][2], sc[mt][2 * c][3]);
                pf[mt][c][2] = packh2(sc[mt][2 * c + 1][0], sc[mt][2 * c + 1][1]);
                pf[mt][c][3] = packh2(sc[mt][2 * c + 1][2], sc[mt][2 * c + 1][3]);
            }

        // O += P @ V
#pragma unroll
        for (int kv = 0; kv < 4; kv++) {
            unsigned vb[8][2];
#pragma unroll
            for (int jp = 0; jp < 4; jp++)
                ldsm4t(vb[2 * jp][0], vb[2 * jp][1], vb[2 * jp + 1][0], vb[2 * jp + 1][1],
                       vbs + (uint32_t)(((kv * 16 + v_krow) * QP2) + jp * 8 + v_jw) * 4);
#pragma unroll
            for (int mt = 0; mt < 2; mt++)
#pragma unroll
                for (int j = 0; j < 8; j++)
                    mma16(o[mt][j][0], o[mt][j][1], o[mt][j][2], o[mt][j][3],
                          pf[mt][kv][0], pf[mt][kv][1], pf[mt][kv][2], pf[mt][kv][3],
                          vb[j][0], vb[j][1]);
        }
    }

    // normalize + write fp16 (B,T,D)
#pragma unroll
    for (int mt = 0; mt < 2; mt++) {
        const float inv0 = 1.0f / l_run[mt][0];
        const float inv1 = 1.0f / l_run[mt][1];
#pragma unroll
        for (int j = 0; j < 8; j++) {
            const int d = h * DHX + j * 8 + t * 2;
            size_t r0 = ((size_t)b * TT + q0 + qb + mt * 16 + g) * DD + d;
            size_t r1 = r0 + (size_t)8 * DD;
            *(__half2*)&g_ctxh[r0] = __floats2half2_rn(o[mt][j][0] * inv0, o[mt][j][1] * inv0);
            *(__half2*)&g_ctxh[r1] = __floats2half2_rn(o[mt][j][2] * inv1, o[mt][j][3] * inv1);
        }
    }
}

// ---------------------------------------------------------------------------
// kernel_launch
// ---------------------------------------------------------------------------
extern "C" void kernel_launch(void* const* d_in, const int* in_sizes, int n_in,
                              void* d_out, int out_size)
{
    const float* query = (const float*)d_in[0];
    const float* key_  = (const float*)d_in[1];
    const float* value = (const float*)d_in[2];
    const float* sp    = (const float*)d_in[3];
    const float* edg   = (const float*)d_in[4];
    const unsigned int* mask = (const unsigned int*)d_in[5];
    const float* Wq = (const float*)d_in[6];
    const float* bq = (const float*)d_in[7];
    const float* Wk = (const float*)d_in[8];
    const float* bk = (const float*)d_in[9];
    const float* Wv = (const float*)d_in[10];
    const float* bv = (const float*)d_in[11];
    const float* Wo = (const float*)d_in[12];
    const float* bo = (const float*)d_in[13];
    float* out = (float*)d_out;

    __half *xq, *xk, *xv, *wq, *wk, *wv, *wo, *gq, *gk, *gv, *gctx;
    cudaGetSymbolAddress((void**)&xq, g_xq);
    cudaGetSymbolAddress((void**)&xk, g_xk);
    cudaGetSymbolAddress((void**)&xv, g_xv);
    cudaGetSymbolAddress((void**)&wq, g_wq);
    cudaGetSymbolAddress((void**)&wk, g_wk);
    cudaGetSymbolAddress((void**)&wv, g_wv);
    cudaGetSymbolAddress((void**)&wo, g_wo);
    cudaGetSymbolAddress((void**)&gq, g_qh);
    cudaGetSymbolAddress((void**)&gk, g_kh);
    cudaGetSymbolAddress((void**)&gv, g_vh);
    cudaGetSymbolAddress((void**)&gctx, g_ctxh);
    float* gb; cudaGetSymbolAddress((void**)&gb, g_bias);

    const int NBIG = MROWS * DD / 4 / 256;   // 8192 blocks
    const int NW   = DD * DD / 4 / 256;      // 1024 blocks
    to_half<<<NBIG, 256>>>((const float4*)query, (uint2*)xq);
    to_half<<<NBIG, 256>>>((const float4*)key_,  (uint2*)xk);
    to_half<<<NBIG, 256>>>((const float4*)value, (uint2*)xv);
    to_half<<<NW, 256>>>((const float4*)Wq, (uint2*)wq);
    to_half<<<NW, 256>>>((const float4*)Wk, (uint2*)wk);
    to_half<<<NW, 256>>>((const float4*)Wv, (uint2*)wv);
    to_half<<<NW, 256>>>((const float4*)Wo, (uint2*)wo);

    bias_fuse<<<BB * TT * TT / 4 / 256, 256>>>((const float4*)sp, (const float4*)edg,
                                               mask, (float4*)gb);

    cudaFuncSetAttribute(gemm_ha<0>, cudaFuncAttributeMaxDynamicSharedMemorySize, GSM);
    cudaFuncSetAttribute(gemm_ha<1>, cudaFuncAttributeMaxDynamicSharedMemorySize, GSM);
    cudaFuncSetAttribute(attn_h, cudaFuncAttributeMaxDynamicSharedMemorySize, ASMEM);

    dim3 grid_qkv(DD / 128, MROWS / 128, 3);
    gemm_ha<0><<<grid_qkv, 256, GSM>>>(xq, xk, xv, wq, wk, wv,
                                       bq, bk, bv, gq, gk, gv);

    dim3 attn_grid(TT / 128, HH, BB);
    attn_h<<<attn_grid, 128, ASMEM>>>(gb);

    dim3 grid_o(DD / 128, MROWS / 128, 1);
    gemm_ha<1><<<grid_o, 256, GSM>>>(gctx, gctx, gctx, wo, wo, wo,
                                     bo, bo, bo, out, out, out);
}

// round 10
// speedup vs baseline: 7.9155x; 1.1121x over previous
#include <cuda_runtime.h>
#include <cuda_fp16.h>
#include <cstdint>

#define BB 8
#define TT 1024
#define DD 1024
#define HH 16
#define DHX 64
#define MROWS (BB*TT)   // 8192

// fp16 scratch
__device__ __half g_xq[MROWS * DD];
__device__ __half g_xk[MROWS * DD];
__device__ __half g_xv[MROWS * DD];
__device__ __half g_wq[DD * DD];
__device__ __half g_wk[DD * DD];
__device__ __half g_wv[DD * DD];
__device__ __half g_wo[DD * DD];
__device__ __half g_qh[MROWS * DD];   // (B,H,T,DH)
__device__ __half g_kh[MROWS * DD];
__device__ __half g_vh[MROWS * DD];
__device__ __half g_ctxh[MROWS * DD]; // (B,T,D)
__device__ float  g_bias[BB * TT * TT];

// ---------------------------------------------------------------------------
// helpers
// ---------------------------------------------------------------------------
__device__ __forceinline__ unsigned packh2(float lo, float hi) {
    __half2 h = __floats2half2_rn(lo, hi);
    return *reinterpret_cast<unsigned*>(&h);
}
__device__ __forceinline__ uint32_t smem_u32(const void* p) {
    uint32_t a;
    asm("{ .reg .u64 t; cvta.to.shared.u64 t, %1; cvt.u32.u64 %0, t; }" : "=r"(a) : "l"(p));
    return a;
}
__device__ __forceinline__ void ldsm4(unsigned& r0, unsigned& r1, unsigned& r2, unsigned& r3,
                                      uint32_t addr) {
    asm volatile("ldmatrix.sync.aligned.m8n8.x4.shared.b16 {%0,%1,%2,%3}, [%4];"
                 : "=r"(r0), "=r"(r1), "=r"(r2), "=r"(r3) : "r"(addr));
}
__device__ __forceinline__ void ldsm4t(unsigned& r0, unsigned& r1, unsigned& r2, unsigned& r3,
                                       uint32_t addr) {
    asm volatile("ldmatrix.sync.aligned.m8n8.x4.trans.shared.b16 {%0,%1,%2,%3}, [%4];"
                 : "=r"(r0), "=r"(r1), "=r"(r2), "=r"(r3) : "r"(addr));
}
__device__ __forceinline__ void mma16(float& c0, float& c1, float& c2, float& c3,
                                      unsigned a0, unsigned a1, unsigned a2, unsigned a3,
                                      unsigned b0, unsigned b1) {
    asm("mma.sync.aligned.m16n8k16.row.col.f32.f16.f16.f32 "
        "{%0,%1,%2,%3}, {%4,%5,%6,%7}, {%8,%9}, {%0,%1,%2,%3};"
        : "+f"(c0), "+f"(c1), "+f"(c2), "+f"(c3)
        : "r"(a0), "r"(a1), "r"(a2), "r"(a3), "r"(b0), "r"(b1));
}
#define CP16(dst, src) \
    asm volatile("cp.async.cg.shared.global [%0], [%1], 16;" :: "r"(dst), "l"(src))
#define CP_COMMIT() asm volatile("cp.async.commit_group;" ::: "memory")
#define CP_WAIT1()  asm volatile("cp.async.wait_group 1;" ::: "memory")
#define PREF_L2(p)  asm volatile("prefetch.global.L2 [%0];" :: "l"(p))

// ---------------------------------------------------------------------------
// f32 -> fp16 conversion, z-batched (3 inputs / 4 weights in one launch)
// ---------------------------------------------------------------------------
__global__ __launch_bounds__(256)
void to_half3(const float4* __restrict__ s0, const float4* __restrict__ s1,
              const float4* __restrict__ s2,
              uint2* __restrict__ d0, uint2* __restrict__ d1, uint2* __restrict__ d2)
{
    const float4* s = (blockIdx.z == 0) ? s0 : (blockIdx.z == 1) ? s1 : s2;
    uint2* d = (blockIdx.z == 0) ? d0 : (blockIdx.z == 1) ? d1 : d2;
    const int i = blockIdx.x * 256 + threadIdx.x;
    float4 v = s[i];
    d[i] = make_uint2(packh2(v.x, v.y), packh2(v.z, v.w));
}
__global__ __launch_bounds__(256)
void to_half4(const float4* __restrict__ s0, const float4* __restrict__ s1,
              const float4* __restrict__ s2, const float4* __restrict__ s3,
              uint2* __restrict__ d0, uint2* __restrict__ d1,
              uint2* __restrict__ d2, uint2* __restrict__ d3)
{
    const float4* s = (blockIdx.z == 0) ? s0 : (blockIdx.z == 1) ? s1 :
                      (blockIdx.z == 2) ? s2 : s3;
    uint2* d = (blockIdx.z == 0) ? d0 : (blockIdx.z == 1) ? d1 :
               (blockIdx.z == 2) ? d2 : d3;
    const int i = blockIdx.x * 256 + threadIdx.x;
    float4 v = s[i];
    d[i] = make_uint2(packh2(v.x, v.y), packh2(v.z, v.w));
}

// ---------------------------------------------------------------------------
// bias pre-fusion: g_bias = mask ? -1e30 : sp + ed  (f32)
// ---------------------------------------------------------------------------
__global__ __launch_bounds__(256)
void bias_fuse(const float4* __restrict__ sp4, const float4* __restrict__ ed4,
               const unsigned* __restrict__ mask, float4* __restrict__ out4)
{
    const int idx = blockIdx.x * 256 + threadIdx.x;
    const int b = idx >> 18;
    const int e4 = idx & 262143;
    const int col = (e4 & 255) << 2;
    const uint4 mk = *(const uint4*)&mask[b * TT + col];
    const float4 s = sp4[idx];
    const float4 e = ed4[idx];
    float4 o;
    o.x = mk.x ? -1e30f : (s.x + e.x);
    o.y = mk.y ? -1e30f : (s.y + e.y);
    o.z = mk.z ? -1e30f : (s.z + e.z);
    o.w = mk.w ? -1e30f : (s.w + e.w);
    out4[idx] = o;
}

// ---------------------------------------------------------------------------
// fp16 cp.async GEMM: C[8192,1024] = A @ W + bias
// BM=128 BN=128 BK=64, 3-stage cp.async, 256 thr = 8 warps (4m x 2n).
// 16 sync epochs (vs 32 at BK=32): 64 mma / 24 ldmatrix per epoch.
// smem word pitches: A 36, B 68 (16B-multiple rows, ldmatrix conflict-free).
// ---------------------------------------------------------------------------
#define AP2 36
#define BP2 68
#define ASTG (128 * AP2)   // 4608 words / stage
#define BSTG (64 * BP2)    // 4352 words / stage
#define GSM  (3 * (ASTG + BSTG) * 4)   // 107520 bytes

template<int MODE>
__global__ __launch_bounds__(256, 2)
void gemm_ha(const __half* __restrict__ A0, const __half* __restrict__ A1, const __half* __restrict__ A2,
             const __half* __restrict__ W0, const __half* __restrict__ W1, const __half* __restrict__ W2,
             const float* __restrict__ bp0, const float* __restrict__ bp1, const float* __restrict__ bp2,
             void* __restrict__ O0, void* __restrict__ O1, void* __restrict__ O2)
{
    extern __shared__ __align__(16) unsigned smw[];
    const uint32_t base = smem_u32(smw);

    const int tid  = threadIdx.x;
    const int lane = tid & 31;
    const int warp = tid >> 5;
    const int g = lane >> 2;
    const int t = lane & 3;
    const int wm = warp >> 1;
    const int wn = warp & 1;
    const int m0 = blockIdx.y * 128;
    const int n0 = blockIdx.x * 128;

    const __half* A = A0; const __half* W = W0; const float* bias = bp0; void* out = O0;
    if (MODE == 0) {
        if (blockIdx.z == 1) { A = A1; W = W1; bias = bp1; out = O1; }
        else if (blockIdx.z == 2) { A = A2; W = W2; bias = bp2; out = O2; }
    }

    const int a_row = (lane & 7) + ((lane >> 3) & 1) * 8;
    const int a_kw  = (lane >> 4) * 4;
    const int b_krow = (lane & 7) + ((lane >> 3) & 1) * 8;
    const int b_j4   = (lane >> 4) * 4;

    auto aw = [&](int s) { return base + (uint32_t)(s * ASTG) * 4; };
    auto bw = [&](int s) { return base + (uint32_t)(3 * ASTG + s * BSTG) * 4; };

    auto issue_stage = [&](int kt, int s) {
        const int k0 = kt * 64;
        const uint32_t ab = aw(s), bb = bw(s);
        // A: 128 rows x 8 chunks (16B)
#pragma unroll
        for (int it = 0; it < 4; it++) {
            int idx = tid + it * 256;
            int m = idx >> 3, ch = idx & 7;
            CP16(ab + (uint32_t)(m * AP2 + ch * 4) * 4,
                 &A[(size_t)(m0 + m) * DD + k0 + ch * 8]);
        }
        // B: 64 k-rows x 16 chunks
#pragma unroll
        for (int it = 0; it < 4; it++) {
            int idx = tid + it * 256;
            int kk = idx >> 4, c = idx & 15;
            CP16(bb + (uint32_t)(kk * BP2 + c * 4) * 4,
                 &W[(size_t)(k0 + kk) * DD + n0 + c * 8]);
        }
    };

    issue_stage(0, 0); CP_COMMIT();
    issue_stage(1, 1); CP_COMMIT();

    float acc[2][8][4];
#pragma unroll
    for (int i = 0; i < 2; i++)
#pragma unroll
        for (int j = 0; j < 8; j++)
#pragma unroll
            for (int c = 0; c < 4; c++) acc[i][j][c] = 0.0f;

    for (int kt = 0; kt < 16; kt++) {
        CP_WAIT1();
        __syncthreads();
        if (kt + 2 < 16) issue_stage(kt + 2, (kt + 2) % 3);
        CP_COMMIT();

        const int s = kt % 3;
        const uint32_t as = aw(s), bs = bw(s);

#pragma unroll
        for (int ks = 0; ks < 4; ks++) {
            unsigned af[2][4];
#pragma unroll
            for (int i = 0; i < 2; i++)
                ldsm4(af[i][0], af[i][1], af[i][2], af[i][3],
                      as + (uint32_t)(((wm * 32 + i * 16 + a_row) * AP2) + ks * 8 + a_kw) * 4);
            unsigned bf[8][2];
#pragma unroll
            for (int jp = 0; jp < 4; jp++)
                ldsm4t(bf[2 * jp][0], bf[2 * jp][1], bf[2 * jp + 1][0], bf[2 * jp + 1][1],
                       bs + (uint32_t)(((ks * 16 + b_krow) * BP2) + wn * 32 + jp * 8 + b_j4) * 4);
#pragma unroll
            for (int i = 0; i < 2; i++)
#pragma unroll
                for (int j = 0; j < 8; j++)
                    mma16(acc[i][j][0], acc[i][j][1], acc[i][j][2], acc[i][j][3],
                          af[i][0], af[i][1], af[i][2], af[i][3],
                          bf[j][0], bf[j][1]);
        }
    }

    // epilogue
#pragma unroll
    for (int i = 0; i < 2; i++) {
#pragma unroll
        for (int j = 0; j < 8; j++) {
            const int n = n0 + wn * 64 + j * 8 + t * 2;
            const float2 bb = *(const float2*)&bias[n];
#pragma unroll
            for (int h2 = 0; h2 < 2; h2++) {
                const int m = m0 + wm * 32 + i * 16 + g + h2 * 8;
                float vx = acc[i][j][h2 * 2 + 0] + bb.x;
                float vy = acc[i][j][h2 * 2 + 1] + bb.y;
                if (MODE == 0) {
                    int bidx = m >> 10, tt = m & 1023;
                    int hh = n >> 6, d = n & 63;
                    __half2 hv = __floats2half2_rn(vx, vy);
                    *(__half2*)&((__half*)out)[(((size_t)(bidx * HH + hh) << 10) + tt) * DHX + d] = hv;
                } else {
                    *(float2*)&((float*)out)[(size_t)m * DD + n] = make_float2(vx, vy);
                }
            }
        }
    }
}

// ---------------------------------------------------------------------------
// Fused flash attention v5: fp16 mma + 3-stage cp.async K/V + bias L2 prefetch.
// Block = (b, h, 128 q-rows), 128 thr = 4 warps, warp = 32 q-rows.
// ---------------------------------------------------------------------------
#define QP2 36
#define QW  (128 * QP2)
#define KVW (64 * QP2)
#define ASMEM ((QW + 3 * 2 * KVW) * 4)   // 73728 bytes

__global__ __launch_bounds__(128)
void attn_h(const float* __restrict__ gb)
{
    extern __shared__ __align__(16) unsigned smw[];
    const uint32_t base = smem_u32(smw);
    unsigned* Q2 = smw;

    const int tid  = threadIdx.x;
    const int lane = tid & 31;
    const int warp = tid >> 5;
    const int g = lane >> 2;
    const int t = lane & 3;
    const int q0 = blockIdx.x * 128;
    const int h  = blockIdx.y;
    const int b  = blockIdx.z;
    const int qb = warp * 32;

    const __half* Qg = g_qh + (size_t)(b * HH + h) * TT * DHX;
    const __half* Kg = g_kh + (size_t)(b * HH + h) * TT * DHX;
    const __half* Vg = g_vh + (size_t)(b * HH + h) * TT * DHX;
    const float* gbrow = &gb[((size_t)b * TT + q0 + tid) * TT];

    const uint32_t sQ = base;
    auto sK = [&](int s) { return base + (uint32_t)(QW + s * 2 * KVW) * 4; };
    auto sV = [&](int s) { return base + (uint32_t)(QW + s * 2 * KVW + KVW) * 4; };

    const int a_row = (lane & 7) + ((lane >> 3) & 1) * 8;
    const int a_kw  = (lane >> 4) * 4;
    const int k_row = (lane & 7) + ((lane >> 4) & 1) * 8;
    const int k_kw  = ((lane >> 3) & 1) * 4;
    const int v_krow = (lane & 7) + ((lane >> 3) & 1) * 8;
    const int v_jw   = (lane >> 4) * 4;

    auto issue_kv = [&](int kt, int s) {
        const int k0 = kt * 64;
        const uint32_t kb = sK(s), vb = sV(s);
#pragma unroll
        for (int it = 0; it < 4; it++) {
            int idx = tid + it * 128;
            int r = idx >> 3, c = idx & 7;
            CP16(kb + (uint32_t)(r * QP2 + c * 4) * 4, &Kg[(size_t)(k0 + r) * DHX + c * 8]);
            CP16(vb + (uint32_t)(r * QP2 + c * 4) * 4, &Vg[(size_t)(k0 + r) * DHX + c * 8]);
        }
    };

    // Q tile + bias warmup for tile 0
#pragma unroll
    for (int it = 0; it < 8; it++) {
        int idx = tid + it * 128;
        int r = idx >> 3, u = idx & 7;
        uint4 qv = *(const uint4*)&Qg[(size_t)(q0 + r) * DHX + u * 8];
        *(uint4*)&Q2[r * QP2 + u * 4] = qv;
    }
    PREF_L2(gbrow);
    PREF_L2(gbrow + 32);
    issue_kv(0, 0); CP_COMMIT();
    issue_kv(1, 1); CP_COMMIT();
    __syncthreads();

    unsigned qf[2][4][4];
#pragma unroll
    for (int mt = 0; mt < 2; mt++)
#pragma unroll
        for (int ks = 0; ks < 4; ks++)
            ldsm4(qf[mt][ks][0], qf[mt][ks][1], qf[mt][ks][2], qf[mt][ks][3],
                  sQ + (uint32_t)(((qb + mt * 16 + a_row) * QP2) + ks * 8 + a_kw) * 4);

    float o[2][8][4];
#pragma unroll
    for (int mt = 0; mt < 2; mt++)
#pragma unroll
        for (int j = 0; j < 8; j++)
#pragma unroll
            for (int c = 0; c < 4; c++) o[mt][j][c] = 0.0f;
    float m_run[2][2] = {{-3e38f, -3e38f}, {-3e38f, -3e38f}};
    float l_run[2][2] = {{0.0f, 0.0f}, {0.0f, 0.0f}};

    for (int kt = 0; kt < 16; kt++) {
        const int k0 = kt * 64;
        CP_WAIT1();
        __syncthreads();
        if (kt + 2 < 16) issue_kv(kt + 2, (kt + 2) % 3);
        CP_COMMIT();

        // prefetch next tile's bias block into L2 (apply-loads then hit L2)
        if (kt + 1 < 16) {
            PREF_L2(gbrow + (kt + 1) * 64);
            PREF_L2(gbrow + (kt + 1) * 64 + 32);
        }

        const int s = kt % 3;
        const uint32_t kbs = sK(s), vbs = sV(s);

        // S = Q K^T
        float sc[2][8][4];
#pragma unroll
        for (int mt = 0; mt < 2; mt++)
#pragma unroll
            for (int j = 0; j < 8; j++)
#pragma unroll
                for (int c = 0; c < 4; c++) sc[mt][j][c] = 0.0f;

#pragma unroll
        for (int ks = 0; ks < 4; ks++) {
            unsigned kb[8][2];
#pragma unroll
            for (int jp = 0; jp < 4; jp++)
                ldsm4(kb[2 * jp][0], kb[2 * jp][1], kb[2 * jp + 1][0], kb[2 * jp + 1][1],
                      kbs + (uint32_t)(((jp * 16 + k_row) * QP2) + ks * 8 + k_kw) * 4);
#pragma unroll
            for (int mt = 0; mt < 2; mt++)
#pragma unroll
                for (int j = 0; j < 8; j++)
                    mma16(sc[mt][j][0], sc[mt][j][1], sc[mt][j][2], sc[mt][j][3],
                          qf[mt][ks][0], qf[mt][ks][1], qf[mt][ks][2], qf[mt][ks][3],
                          kb[j][0], kb[j][1]);
        }

        // scale + fused bias (f32)
#pragma unroll
        for (int mt = 0; mt < 2; mt++)
#pragma unroll
            for (int j = 0; j < 8; j++) {
                const int col = k0 + j * 8 + t * 2;
                const size_t i0 = ((size_t)b * TT + (q0 + qb + mt * 16 + g)) * TT + col;
                float2 b0 = *(const float2*)&gb[i0];
                float2 b1 = *(const float2*)&gb[i0 + (size_t)8 * TT];
                sc[mt][j][0] = sc[mt][j][0] * 0.125f + b0.x;
                sc[mt][j][1] = sc[mt][j][1] * 0.125f + b0.y;
                sc[mt][j][2] = sc[mt][j][2] * 0.125f + b1.x;
                sc[mt][j][3] = sc[mt][j][3] * 0.125f + b1.y;
            }

        // online softmax
#pragma unroll
        for (int mt = 0; mt < 2; mt++)
#pragma unroll
            for (int r = 0; r < 2; r++) {
                float mx = -3e38f;
#pragma unroll
                for (int j = 0; j < 8; j++)
                    mx = fmaxf(mx, fmaxf(sc[mt][j][2 * r], sc[mt][j][2 * r + 1]));
                mx = fmaxf(mx, __shfl_xor_sync(0xffffffffu, mx, 1));
                mx = fmaxf(mx, __shfl_xor_sync(0xffffffffu, mx, 2));
                float m_new = fmaxf(m_run[mt][r], mx);
                float alpha = __expf(m_run[mt][r] - m_new);
                m_run[mt][r] = m_new;
                float ls = 0.0f;
#pragma unroll
                for (int j = 0; j < 8; j++) {
                    float p0 = __expf(sc[mt][j][2 * r] - m_new);
                    float p1 = __expf(sc[mt][j][2 * r + 1] - m_new);
                    sc[mt][j][2 * r] = p0; sc[mt][j][2 * r + 1] = p1;
                    ls += p0 + p1;
                }
                ls += __shfl_xor_sync(0xffffffffu, ls, 1);
                ls += __shfl_xor_sync(0xffffffffu, ls, 2);
                l_run[mt][r] = l_run[mt][r] * alpha + ls;
#pragma unroll
                for (int j = 0; j < 8; j++) {
                    o[mt][j][2 * r] *= alpha;
                    o[mt][j][2 * r + 1] *= alpha;
                }
            }

        // pack P into A fragments in registers
        unsigned pf[2][4][4];
#pragma unroll
        for (int mt = 0; mt < 2; mt++)
#pragma unroll
            for (int c = 0; c < 4; c++) {
                pf[mt][c][0] = packh2(sc[mt][2 * c][0], sc[mt][2 * c][1]);
                pf[mt][c][1] = packh2(sc[mt][2 * c][2], sc[mt][2 * c][3]);
                pf[mt][c][2] = packh2(sc[mt][2 * c + 1][0], sc[mt][2 * c + 1][1]);
                pf[mt][c][3] = packh2(sc[mt][2 * c + 1][2], sc[mt][2 * c + 1][3]);
            }

        // O += P @ V
#pragma unroll
        for (int kv = 0; kv < 4; kv++) {
            unsigned vb[8][2];
#pragma unroll
            for (int jp = 0; jp < 4; jp++)
                ldsm4t(vb[2 * jp][0], vb[2 * jp][1], vb[2 * jp + 1][0], vb[2 * jp + 1][1],
                       vbs + (uint32_t)(((kv * 16 + v_krow) * QP2) + jp * 8 + v_jw) * 4);
#pragma unroll
            for (int mt = 0; mt < 2; mt++)
#pragma unroll
                for (int j = 0; j < 8; j++)
                    mma16(o[mt][j][0], o[mt][j][1], o[mt][j][2], o[mt][j][3],
                          pf[mt][kv][0], pf[mt][kv][1], pf[mt][kv][2], pf[mt][kv][3],
                          vb[j][0], vb[j][1]);
        }
    }

    // normalize + write fp16 (B,T,D)
#pragma unroll
    for (int mt = 0; mt < 2; mt++) {
        const float inv0 = 1.0f / l_run[mt][0];
        const float inv1 = 1.0f / l_run[mt][1];
#pragma unroll
        for (int j = 0; j < 8; j++) {
            const int d = h * DHX + j * 8 + t * 2;
            size_t r0 = ((size_t)b * TT + q0 + qb + mt * 16 + g) * DD + d;
            size_t r1 = r0 + (size_t)8 * DD;
            *(__half2*)&g_ctxh[r0] = __floats2half2_rn(o[mt][j][0] * inv0, o[mt][j][1] * inv0);
            *(__half2*)&g_ctxh[r1] = __floats2half2_rn(o[mt][j][2] * inv1, o[mt][j][3] * inv1);
        }
    }
}

// ---------------------------------------------------------------------------
// kernel_launch
// ---------------------------------------------------------------------------
extern "C" void kernel_launch(void* const* d_in, const int* in_sizes, int n_in,
                              void* d_out, int out_size)
{
    const float* query = (const float*)d_in[0];
    const float* key_  = (const float*)d_in[1];
    const float* value = (const float*)d_in[2];
    const float* sp    = (const float*)d_in[3];
    const float* edg   = (const float*)d_in[4];
    const unsigned int* mask = (const unsigned int*)d_in[5];
    const float* Wq = (const float*)d_in[6];
    const float* bq = (const float*)d_in[7];
    const float* Wk = (const float*)d_in[8];
    const float* bk = (const float*)d_in[9];
    const float* Wv = (const float*)d_in[10];
    const float* bv = (const float*)d_in[11];
    const float* Wo = (const float*)d_in[12];
    const float* bo = (const float*)d_in[13];
    float* out = (float*)d_out;

    __half *xq, *xk, *xv, *wq, *wk, *wv, *wo, *gq, *gk, *gv, *gctx;
    cudaGetSymbolAddress((void**)&xq, g_xq);
    cudaGetSymbolAddress((void**)&xk, g_xk);
    cudaGetSymbolAddress((void**)&xv, g_xv);
    cudaGetSymbolAddress((void**)&wq, g_wq);
    cudaGetSymbolAddress((void**)&wk, g_wk);
    cudaGetSymbolAddress((void**)&wv, g_wv);
    cudaGetSymbolAddress((void**)&wo, g_wo);
    cudaGetSymbolAddress((void**)&gq, g_qh);
    cudaGetSymbolAddress((void**)&gk, g_kh);
    cudaGetSymbolAddress((void**)&gv, g_vh);
    cudaGetSymbolAddress((void**)&gctx, g_ctxh);
    float* gb; cudaGetSymbolAddress((void**)&gb, g_bias);

    dim3 gin(MROWS * DD / 4 / 256, 1, 3);   // (8192,1,3)
    to_half3<<<gin, 256>>>((const float4*)query, (const float4*)key_, (const float4*)value,
                           (uint2*)xq, (uint2*)xk, (uint2*)xv);
    dim3 gw(DD * DD / 4 / 256, 1, 4);       // (1024,1,4)
    to_half4<<<gw, 256>>>((const float4*)Wq, (const float4*)Wk, (const float4*)Wv, (const float4*)Wo,
                          (uint2*)wq, (uint2*)wk, (uint2*)wv, (uint2*)wo);

    bias_fuse<<<BB * TT * TT / 4 / 256, 256>>>((const float4*)sp, (const float4*)edg,
                                               mask, (float4*)gb);

    cudaFuncSetAttribute(gemm_ha<0>, cudaFuncAttributeMaxDynamicSharedMemorySize, GSM);
    cudaFuncSetAttribute(gemm_ha<1>, cudaFuncAttributeMaxDynamicSharedMemorySize, GSM);
    cudaFuncSetAttribute(attn_h, cudaFuncAttributeMaxDynamicSharedMemorySize, ASMEM);

    dim3 grid_qkv(DD / 128, MROWS / 128, 3);
    gemm_ha<0><<<grid_qkv, 256, GSM>>>(xq, xk, xv, wq, wk, wv,
                                       bq, bk, bv, gq, gk, gv);

    dim3 attn_grid(TT / 128, HH, BB);
    attn_h<<<attn_grid, 128, ASMEM>>>(gb);

    dim3 grid_o(DD / 128, MROWS / 128, 1);
    gemm_ha<1><<<grid_o, 256, GSM>>>(gctx, gctx, gctx, wo, wo, wo,
                                     bo, bo, bo, out, out, out);
}